// round 13
// baseline (speedup 1.0000x reference)
#include <cuda_runtime.h>
#include <cstdint>

#define NN 50000
#define NE 600000
#define NG 64
#define D  128
#define NCLS 10
#define NT_E  (NE / 64)            // 9375 (exact)
#define NT64  ((NN + 63) / 64)     // 782

#define GEC 1120                   // edge CTAs in combined kernel
#define GNC 160                    // node phase-2 CTAs
#define GTOT 1280                  // combined grid (every 8th CTA = node)

#define LDKB 272                   // bf16 tile row stride in bytes
#define LDC  132                   // float stage stride (floats)

// ---- 64-row kernel smem map (bytes), total 104448 -> 2 CTAs/SM ----
#define SO64_AH 0
#define SO64_AL 17408
#define SO64_WH 34816
#define SO64_WL 69632
#define SM64    104448

// ---------------- scratch (static device globals) ---------------------------
__device__ float g_edge[NE * D];        // updated edge features
__device__ float g_node[NN * D];
__device__ float g_NW[NN * 2 * D];      // [node][NW1(128) | NW2(128)]
__device__ float g_tmp[NN * D];         // node @ Wn1 partial (computed in edge kernel)
__device__ float g_ebar[NN * D];        // per-dst edge sums (RED target)
__device__ float g_u[NG * D];
__device__ float g_uprojE[NG * D];
__device__ float g_uprojN[NG * D];
__device__ float g_gsum_node[NG * D];
__device__ float g_gsum_ebar[NG * D];
__device__ float g_nm[NG * D];          // per-pass node means (readout)
__device__ float g_em[NG * D];          // per-pass ebar means
__device__ float g_indeg[NN];
__device__ float g_cntg[NG];
__device__ uint4 g_Wimg[5][2][2048];    // bf16 [n][k] compact W images, hi/lo

// ---------------- helpers ------------------------------------------------
__device__ __forceinline__ uint32_t smem_to_u32(const void* p) {
    uint32_t a;
    asm("{ .reg .u64 t; cvta.to.shared.u64 t, %1; cvt.u32.u64 %0, t; }" : "=r"(a) : "l"(p));
    return a;
}
__device__ __forceinline__ uint32_t cvt2(float odd, float even) {
    uint32_t r;
    asm("cvt.rn.bf16x2.f32 %0, %1, %2;" : "=r"(r) : "f"(odd), "f"(even));
    return r;
}
__device__ __forceinline__ void split8(const float* f, uint4& hi, uint4& lo) {
    uint32_t h[4];
    float rr[8];
#pragma unroll
    for (int q = 0; q < 4; q++) {
        h[q] = cvt2(f[2 * q + 1], f[2 * q]);
        rr[2 * q]     = f[2 * q]     - __uint_as_float(h[q] << 16);
        rr[2 * q + 1] = f[2 * q + 1] - __uint_as_float(h[q] & 0xffff0000u);
    }
    hi = make_uint4(h[0], h[1], h[2], h[3]);
    lo = make_uint4(cvt2(rr[1], rr[0]), cvt2(rr[3], rr[2]), cvt2(rr[5], rr[4]), cvt2(rr[7], rr[6]));
}
__device__ __forceinline__ void split4(float4 f, uint2& hi, uint2& lo) {
    uint32_t h0 = cvt2(f.y, f.x), h1 = cvt2(f.w, f.z);
    float r0 = f.x - __uint_as_float(h0 << 16);
    float r1 = f.y - __uint_as_float(h0 & 0xffff0000u);
    float r2 = f.z - __uint_as_float(h1 << 16);
    float r3 = f.w - __uint_as_float(h1 & 0xffff0000u);
    hi = make_uint2(h0, h1);
    lo = make_uint2(cvt2(r1, r0), cvt2(r3, r2));
}
__device__ __forceinline__ void red_add_v4(float* p, float a, float b, float c, float d) {
    asm volatile("red.global.add.v4.f32 [%0], {%1,%2,%3,%4};"
                 :: "l"(p), "f"(a), "f"(b), "f"(c), "f"(d) : "memory");
}
__device__ __forceinline__ void ldm4(uint32_t addr, uint32_t r[4]) {
    asm volatile("ldmatrix.sync.aligned.m8n8.x4.shared.b16 {%0,%1,%2,%3}, [%4];"
                 : "=r"(r[0]), "=r"(r[1]), "=r"(r[2]), "=r"(r[3]) : "r"(addr));
}
__device__ __forceinline__ void mma16816(float c[4], const uint32_t a[4], uint32_t b0, uint32_t b1) {
    asm volatile("mma.sync.aligned.m16n8k16.row.col.f32.bf16.bf16.f32 "
                 "{%0,%1,%2,%3}, {%4,%5,%6,%7}, {%8,%9}, {%0,%1,%2,%3};"
                 : "+f"(c[0]), "+f"(c[1]), "+f"(c[2]), "+f"(c[3])
                 : "r"(a[0]), "r"(a[1]), "r"(a[2]), "r"(a[3]), "r"(b0), "r"(b1));
}

// ============ 64-row GEMM engine: 256 threads, 8 warps (2m x 4n) ============
__device__ __forceinline__ void mainloop64(uint32_t smb, float acc[2][4][4], int lane, int wm, int wn)
{
    uint32_t aoff = (uint32_t)((wm * 32 + (lane & 7) + ((lane >> 3) & 1) * 8) * LDKB
                               + ((lane >> 4) & 1) * 16);
    uint32_t boff = (uint32_t)((wn * 32 + (lane & 7) + ((lane >> 4) & 1) * 8) * LDKB
                               + ((lane >> 3) & 1) * 16);
    uint32_t aH = smb + SO64_AH + aoff;
    uint32_t aL = smb + SO64_AL + aoff;
    uint32_t bH = smb + SO64_WH + boff;
    uint32_t bL = smb + SO64_WL + boff;
#pragma unroll
    for (int ks = 0; ks < 8; ks++) {
        uint32_t ah[2][4], al[2][4], b[2][4];
#pragma unroll
        for (int mf = 0; mf < 2; mf++) {
            ldm4(aH + mf * 16 * LDKB + ks * 32, ah[mf]);
            ldm4(aL + mf * 16 * LDKB + ks * 32, al[mf]);
        }
#pragma unroll
        for (int np = 0; np < 2; np++) ldm4(bH + np * 16 * LDKB + ks * 32, b[np]);
#pragma unroll
        for (int mf = 0; mf < 2; mf++)
#pragma unroll
            for (int nf = 0; nf < 4; nf++)
                mma16816(acc[mf][nf], ah[mf], b[nf >> 1][(nf & 1) * 2], b[nf >> 1][(nf & 1) * 2 + 1]);
#pragma unroll
        for (int mf = 0; mf < 2; mf++)
#pragma unroll
            for (int nf = 0; nf < 4; nf++)
                mma16816(acc[mf][nf], al[mf], b[nf >> 1][(nf & 1) * 2], b[nf >> 1][(nf & 1) * 2 + 1]);
#pragma unroll
        for (int np = 0; np < 2; np++) ldm4(bL + np * 16 * LDKB + ks * 32, b[np]);
#pragma unroll
        for (int mf = 0; mf < 2; mf++)
#pragma unroll
            for (int nf = 0; nf < 4; nf++)
                mma16816(acc[mf][nf], ah[mf], b[nf >> 1][(nf & 1) * 2], b[nf >> 1][(nf & 1) * 2 + 1]);
    }
}
__device__ __forceinline__ void acc_zero64(float acc[2][4][4]) {
#pragma unroll
    for (int i = 0; i < 2; i++)
#pragma unroll
        for (int j = 0; j < 4; j++)
#pragma unroll
            for (int q = 0; q < 4; q++) acc[i][j][q] = 0.f;
}
__device__ __forceinline__ void stage64(float* smC, const float acc[2][4][4],
                                        int lane, int wm, int wn)
{
    int qr = lane >> 2, qc = (lane & 3) * 2;
#pragma unroll
    for (int mf = 0; mf < 2; mf++)
#pragma unroll
        for (int nf = 0; nf < 4; nf++) {
            float* p = smC + (wm * 32 + mf * 16 + qr) * LDC + wn * 32 + nf * 8 + qc;
            p[0] = acc[mf][nf][0];
            p[1] = acc[mf][nf][1];
            p[8 * LDC] = acc[mf][nf][2];
            p[8 * LDC + 1] = acc[mf][nf][3];
        }
}
__device__ __forceinline__ void copy_w64(char* sm, int m, int t)
{
    const uint4* sh = g_Wimg[m][0];
    const uint4* sl = g_Wimg[m][1];
#pragma unroll
    for (int i = t; i < 2048; i += 256) {
        int dst = (i >> 4) * LDKB + (i & 15) * 16;
        *(uint4*)(sm + SO64_WH + dst) = sh[i];
        *(uint4*)(sm + SO64_WL + dst) = sl[i];
    }
}
__device__ __forceinline__ void store_a64(char* sm, int r, int c8, const float* f)
{
    uint4 hi, lo; split8(f, hi, lo);
    int off = r * LDKB + c8 * 2;
    *(uint4*)(sm + SO64_AH + off) = hi;
    *(uint4*)(sm + SO64_AL + off) = lo;
}

// ---------------- k_setup: wprep + uproj(from u_in) + zero/copy ---------------
__global__ void k_setup(const float* __restrict__ u_in,
                        const float* __restrict__ We_w, const float* __restrict__ We_b,
                        const float* __restrict__ Wn_w, const float* __restrict__ Wn_b)
{
    int b = blockIdx.x, t = threadIdx.x;
    if (b < 5) {
        const float* W = (b == 0) ? We_w
                       : (b == 1) ? We_w + D * D
                       : (b == 2) ? We_w + 2 * D * D
                       : (b == 3) ? Wn_w
                                  : Wn_w + D * D;
        uint4* ih = g_Wimg[b][0];
        uint4* il = g_Wimg[b][1];
        for (int g = t; g < 2048; g += 256) {
            int n = g >> 4, c8 = (g & 15) << 3;
            float f[8];
#pragma unroll
            for (int j = 0; j < 8; j++) f[j] = W[(c8 + j) * D + n];
            uint4 hi, lo;
            split8(f, hi, lo);
            ih[g] = hi;
            il[g] = lo;
        }
    } else if (b < 69) {
        int g = b - 5;
        __shared__ float us[D];
        if (t < D) us[t] = u_in[g * D + t];
        __syncthreads();
        if (t < D) {
            int j = t;
            float aE = We_b[j], aN = Wn_b[j];
#pragma unroll 4
            for (int k = 0; k < D; k++) {
                float uv = us[k];
                aE = fmaf(uv, We_w[(3 * D + k) * D + j], aE);
                aN = fmaf(uv, Wn_w[(2 * D + k) * D + j], aN);
            }
            g_uprojE[g * D + j] = aE;
            g_uprojN[g * D + j] = aN;
            g_u[g * D + j] = us[j];
        }
    } else {
        int z = b - 69;
        int idx = z * 256 + t;
        int stride = 256 * 256;
        for (int x = idx; x < NN * D / 4; x += stride)
            ((float4*)g_ebar)[x] = make_float4(0.f, 0.f, 0.f, 0.f);
        for (int x = idx; x < NN; x += stride) g_indeg[x] = 0.f;
        if (idx < NG) g_cntg[idx] = 0.f;
        if (idx < NG * D) { g_gsum_node[idx] = 0.f; g_gsum_ebar[idx] = 0.f; }
    }
}
__global__ void k_hist(const int* __restrict__ ei, const int* __restrict__ batch)
{
    int i = blockIdx.x * blockDim.x + threadIdx.x;
    if (i < NE) atomicAdd(&g_indeg[ei[NE + i]], 1.f);
    if (i < NN) atomicAdd(&g_cntg[batch[i]], 1.f);
}

// ---------------- k_proj (pass 0 only): NW = node_in @ [We1|We2] --------------
__global__ void __launch_bounds__(256, 2) k_proj(const float* __restrict__ Nsrc)
{
    extern __shared__ char sm[];
    uint32_t smb = smem_to_u32(sm);
    int t = threadIdx.x, lane = t & 31, wid = t >> 5;
    int wm = wid >> 2, wn = wid & 3;
    int n0 = blockIdx.x * 64;

#pragma unroll
    for (int u = 0; u < 4; u++) {
        int g = t + u * 256;
        int r = g >> 4, c8 = (g & 15) << 3;
        int n = n0 + r;
        float f[8] = {0, 0, 0, 0, 0, 0, 0, 0};
        if (n < NN) { *(float4*)f = *(const float4*)(Nsrc + (size_t)n * D + c8);
                      *(float4*)(f + 4) = *(const float4*)(Nsrc + (size_t)n * D + c8 + 4); }
        store_a64(sm, r, c8, f);
    }
#pragma unroll
    for (int half = 0; half < 2; half++) {
        copy_w64(sm, half, t);                // We1 then We2
        __syncthreads();
        float acc[2][4][4];
        acc_zero64(acc);
        mainloop64(smb, acc, lane, wm, wn);
        __syncthreads();
        stage64((float*)(sm + SO64_WH), acc, lane, wm, wn);
        __syncthreads();
#pragma unroll
        for (int rr = 0; rr < 8; rr++) {
            int r = wid * 8 + rr;
            int n = n0 + r;
            if (n < NN) {
                float4 v = *(const float4*)((const float*)(sm + SO64_WH) + r * LDC + lane * 4);
                *(float4*)(g_NW + (size_t)n * 256 + half * 128 + lane * 4) = v;
            }
        }
        __syncthreads();
    }
}

// ---- combined kernel: edge update CTAs + node@Wn1 (g_tmp) CTAs ----------------
// bid & 7 == 7  -> node phase-2 CTA (nid = bid>>3), else edge CTA (eid = bid - (bid>>3))
__global__ void __launch_bounds__(256, 2) k_edge_node(const float* __restrict__ Eattr,
                                                      const int* __restrict__ ei,
                                                      const int* __restrict__ batch,
                                                      const float* __restrict__ Nsrc,
                                                      int last)
{
    extern __shared__ char sm[];
    uint32_t smb = smem_to_u32(sm);
    int t = threadIdx.x, lane = t & 31, wid = t >> 5;
    int wm = wid >> 2, wn = wid & 3;
    int bid = blockIdx.x;

    if ((bid & 7) == 7) {
        // ---------------- node phase-2: g_tmp = node @ Wn1 ----------------
        int nid = bid >> 3;
        copy_w64(sm, 3, t);                   // Wn1
        __syncthreads();
        for (int tile = nid; tile < NT64; tile += GNC) {
            int n0 = tile * 64;
#pragma unroll
            for (int u = 0; u < 4; u++) {
                int g = t + u * 256;
                int r = g >> 4, c8 = (g & 15) << 3;
                int n = n0 + r;
                float f[8] = {0, 0, 0, 0, 0, 0, 0, 0};
                if (n < NN) { *(float4*)f = *(const float4*)(Nsrc + (size_t)n * D + c8);
                              *(float4*)(f + 4) = *(const float4*)(Nsrc + (size_t)n * D + c8 + 4); }
                store_a64(sm, r, c8, f);
            }
            __syncthreads();
            float acc[2][4][4];
            acc_zero64(acc);
            mainloop64(smb, acc, lane, wm, wn);
            __syncthreads();
            stage64((float*)sm, acc, lane, wm, wn);
            __syncthreads();
#pragma unroll
            for (int rr = 0; rr < 8; rr++) {
                int r = wid * 8 + rr;
                int n = n0 + r;
                if (n < NN) {
                    float4 v = *(const float4*)((const float*)sm + r * LDC + lane * 4);
                    *(float4*)(g_tmp + (size_t)n * D + lane * 4) = v;
                }
            }
            __syncthreads();
        }
        return;
    }

    // ---------------- edge update: relu(e@We3 + NW1[src] + NW2[dst] + uprojE) --
    int eid = bid - (bid >> 3);
    copy_w64(sm, 2, t);                       // We3
    int r0 = t >> 4, c8v = (t & 15) << 3;
    float4 pf[8];
    int tile = eid;
    if (tile < NT_E) {
        const float* base = Eattr + (size_t)(tile * 64) * D;
#pragma unroll
        for (int u = 0; u < 4; u++) {
            const float* p = base + (size_t)(r0 + u * 16) * D + c8v;
            pf[u * 2]     = *(const float4*)p;
            pf[u * 2 + 1] = *(const float4*)(p + 4);
        }
    }
    __syncthreads();

    for (; tile < NT_E; tile += GEC) {
        int e0 = tile * 64;
#pragma unroll
        for (int u = 0; u < 4; u++) {
            float f[8];
            *(float4*)f       = pf[u * 2];
            *(float4*)(f + 4) = pf[u * 2 + 1];
            store_a64(sm, r0 + u * 16, c8v, f);
        }
        __syncthreads();
        float acc[2][4][4];
        acc_zero64(acc);
        mainloop64(smb, acc, lane, wm, wn);
        __syncthreads();
        stage64((float*)sm, acc, lane, wm, wn);
        // prefetch next tile while epilogue runs
        int nxt = tile + GEC;
        if (nxt < NT_E) {
            const float* base = Eattr + (size_t)(nxt * 64) * D;
#pragma unroll
            for (int u = 0; u < 4; u++) {
                const float* p = base + (size_t)(r0 + u * 16) * D + c8v;
                pf[u * 2]     = *(const float4*)p;
                pf[u * 2 + 1] = *(const float4*)(p + 4);
            }
        }
        __syncthreads();
#pragma unroll
        for (int rr = 0; rr < 8; rr++) {
            int r = wid * 8 + rr;
            int e = e0 + r;
            int sN = ei[e], dN = ei[NE + e], gb = batch[sN];
            float4 c = *(const float4*)((const float*)sm + r * LDC + lane * 4);
            float4 a = *(const float4*)(g_NW + (size_t)sN * 256 + lane * 4);
            float4 b = *(const float4*)(g_NW + (size_t)dN * 256 + 128 + lane * 4);
            float4 u = *(const float4*)(g_uprojE + (size_t)gb * D + lane * 4);
            float y0 = fmaxf(c.x + a.x + b.x + u.x, 0.f);
            float y1 = fmaxf(c.y + a.y + b.y + u.y, 0.f);
            float y2 = fmaxf(c.z + a.z + b.z + u.z, 0.f);
            float y3 = fmaxf(c.w + a.w + b.w + u.w, 0.f);
            if (!last) *(float4*)(g_edge + (size_t)e * D + lane * 4) = make_float4(y0, y1, y2, y3);
            red_add_v4(g_ebar + (size_t)dN * D + lane * 4, y0, y1, y2, y3);
        }
        __syncthreads();
    }
}

// ---- k_node2: y = relu(ebar@Wn2 + g_tmp + uprojN); then NW = y @ [We1|We2] ----
__global__ void __launch_bounds__(256, 2) k_node2(const int* __restrict__ batch, int last)
{
    extern __shared__ char sm[];
    uint32_t smb = smem_to_u32(sm);
    int t = threadIdx.x, lane = t & 31, wid = t >> 5;
    int wm = wid >> 2, wn = wid & 3;
    int n0 = blockIdx.x * 64;
    float* smS = (float*)(sm + SO64_WH);    // stage region (W dead when used)

    // A = ebar*inv_deg (zero in place, gsum_ebar RED), W = Wn2
    copy_w64(sm, 4, t);
    const float4 z4 = make_float4(0.f, 0.f, 0.f, 0.f);
#pragma unroll
    for (int u = 0; u < 4; u++) {
        int g = t + u * 256;
        int r = g >> 4, c8 = (g & 15) << 3;
        int n = n0 + r;
        float f[8] = {0, 0, 0, 0, 0, 0, 0, 0};
        if (n < NN) {
            float inv = 1.f / fmaxf(g_indeg[n], 1.f);
            float4 v0 = *(const float4*)(g_ebar + (size_t)n * D + c8);
            float4 v1 = *(const float4*)(g_ebar + (size_t)n * D + c8 + 4);
            *(float4*)(g_ebar + (size_t)n * D + c8)     = z4;
            *(float4*)(g_ebar + (size_t)n * D + c8 + 4) = z4;
            f[0] = v0.x * inv; f[1] = v0.y * inv; f[2] = v0.z * inv; f[3] = v0.w * inv;
            f[4] = v1.x * inv; f[5] = v1.y * inv; f[6] = v1.z * inv; f[7] = v1.w * inv;
            float* pg = g_gsum_ebar + (size_t)batch[n] * D + c8;
            red_add_v4(pg,     f[0], f[1], f[2], f[3]);
            red_add_v4(pg + 4, f[4], f[5], f[6], f[7]);
        }
        store_a64(sm, r, c8, f);
    }
    __syncthreads();

    float acc[2][4][4];
    acc_zero64(acc);
    mainloop64(smb, acc, lane, wm, wn);     // ebar @ Wn2
    __syncthreads();
    stage64(smS, acc, lane, wm, wn);        // over W region (dead)
    __syncthreads();

    // epilogue: y = relu(stage + g_tmp + uprojN); store node/gsum; re-split y into A
#pragma unroll
    for (int rr = 0; rr < 8; rr++) {
        int r = wid * 8 + rr;
        int n = n0 + r;
        if (n < NN) {
            int gb = batch[n];
            float4 c = *(const float4*)(smS + r * LDC + lane * 4);
            float4 w = *(const float4*)(g_tmp + (size_t)n * D + lane * 4);
            float4 u = *(const float4*)(g_uprojN + (size_t)gb * D + lane * 4);
            float4 y = make_float4(fmaxf(c.x + w.x + u.x, 0.f), fmaxf(c.y + w.y + u.y, 0.f),
                                   fmaxf(c.z + w.z + u.z, 0.f), fmaxf(c.w + w.w + u.w, 0.f));
            red_add_v4(g_gsum_node + (size_t)gb * D + lane * 4, y.x, y.y, y.z, y.w);
            if (!last) {
                *(float4*)(g_node + (size_t)n * D + lane * 4) = y;
                uint2 hi, lo;
                split4(y, hi, lo);
                int off = r * LDKB + lane * 8;
                *(uint2*)(sm + SO64_AH + off) = hi;
                *(uint2*)(sm + SO64_AL + off) = lo;
            }
        } else if (!last) {
            int off = r * LDKB + lane * 8;
            *(uint2*)(sm + SO64_AH + off) = make_uint2(0u, 0u);
            *(uint2*)(sm + SO64_AL + off) = make_uint2(0u, 0u);
        }
    }

    // NW for next pass: NW1|NW2 = y @ [We1|We2]
    if (!last) {
#pragma unroll
        for (int half = 0; half < 2; half++) {
            __syncthreads();                 // A ready / prev stage reads done
            copy_w64(sm, half, t);           // We1 then We2
            __syncthreads();
            float accp[2][4][4];
            acc_zero64(accp);
            mainloop64(smb, accp, lane, wm, wn);
            __syncthreads();
            stage64(smS, accp, lane, wm, wn);
            __syncthreads();
#pragma unroll
            for (int rr = 0; rr < 8; rr++) {
                int r = wid * 8 + rr;
                int n = n0 + r;
                if (n < NN) {
                    float4 v = *(const float4*)(smS + r * LDC + lane * 4);
                    *(float4*)(g_NW + (size_t)n * 256 + half * 128 + lane * 4) = v;
                }
            }
        }
    }
}

// ---------------- global update + means store + gsum reset ---------------------
__global__ void k_global(const float* __restrict__ Wg_w, const float* __restrict__ Wg_b,
                         const float* __restrict__ We_w, const float* __restrict__ We_b,
                         const float* __restrict__ Wn_w, const float* __restrict__ Wn_b)
{
    int g = blockIdx.x, j = threadIdx.x;
    __shared__ float nm[D], em[D], uu[D], un[D];
    float inv = 1.f / fmaxf(g_cntg[g], 1.f);
    float nmv = g_gsum_node[g * D + j] * inv;
    float emv = g_gsum_ebar[g * D + j] * inv;
    nm[j] = nmv; em[j] = emv;
    uu[j] = g_u[g * D + j];
    g_nm[g * D + j] = nmv;
    g_em[g * D + j] = emv;
    g_gsum_node[g * D + j] = 0.f;
    g_gsum_ebar[g * D + j] = 0.f;
    __syncthreads();
    float acc = Wg_b[j];
#pragma unroll 4
    for (int k = 0; k < D; k++) {
        acc = fmaf(nm[k], Wg_w[k * D + j], acc);
        acc = fmaf(em[k], Wg_w[(D + k) * D + j], acc);
        acc = fmaf(uu[k], Wg_w[(2 * D + k) * D + j], acc);
    }
    float r = fmaxf(acc, 0.f);
    g_u[g * D + j] = r;
    un[j] = r;
    __syncthreads();
    float aE = We_b[j], aN = Wn_b[j];
#pragma unroll 4
    for (int k = 0; k < D; k++) {
        float uv = un[k];
        aE = fmaf(uv, We_w[(3 * D + k) * D + j], aE);
        aN = fmaf(uv, Wn_w[(2 * D + k) * D + j], aN);
    }
    g_uprojE[g * D + j] = aE;
    g_uprojN[g * D + j] = aN;
}

__global__ void k_readout(const float* __restrict__ lin_w, const float* __restrict__ lin_b,
                          float* __restrict__ out)
{
    int g = blockIdx.x, t = threadIdx.x;
    __shared__ float pooled[3 * D];
    pooled[t]         = g_nm[g * D + t];
    pooled[D + t]     = g_em[g * D + t];
    pooled[2 * D + t] = g_u[g * D + t];
    __syncthreads();
    if (t < NCLS) {
        float acc = lin_b[t];
#pragma unroll 4
        for (int k = 0; k < 3 * D; k++) acc = fmaf(pooled[k], lin_w[k * NCLS + t], acc);
        out[g * NCLS + t] = acc;
    }
}

// ---------------- host launcher ----------------------------------------------
extern "C" void kernel_launch(void* const* d_in, const int* in_sizes, int n_in,
                              void* d_out, int out_size)
{
    const float* node_in = (const float*)d_in[0];
    const float* edge_in = (const float*)d_in[1];
    const float* u_in    = (const float*)d_in[2];
    const int*   ei      = (const int*)d_in[3];
    const int*   batch   = (const int*)d_in[4];
    const float* We_w = (const float*)d_in[5];
    const float* We_b = (const float*)d_in[6];
    const float* Wn_w = (const float*)d_in[7];
    const float* Wn_b = (const float*)d_in[8];
    const float* Wg_w = (const float*)d_in[9];
    const float* Wg_b = (const float*)d_in[10];
    const float* lin_w = (const float*)d_in[11];
    const float* lin_b = (const float*)d_in[12];
    float* out = (float*)d_out;

    float *p_node = nullptr, *p_edge = nullptr;
    cudaGetSymbolAddress((void**)&p_node, g_node);
    cudaGetSymbolAddress((void**)&p_edge, g_edge);

    cudaFuncSetAttribute(k_proj,      cudaFuncAttributeMaxDynamicSharedMemorySize, SM64);
    cudaFuncSetAttribute(k_edge_node, cudaFuncAttributeMaxDynamicSharedMemorySize, SM64);
    cudaFuncSetAttribute(k_node2,     cudaFuncAttributeMaxDynamicSharedMemorySize, SM64);

    k_setup<<<325, 256>>>(u_in, We_w, We_b, Wn_w, Wn_b);   // 0
    k_hist<<<(NE + 255) / 256, 256>>>(ei, batch);          // 1
    k_proj<<<NT64, 256, SM64>>>(node_in);                  // 2 (once)

    const float* nsrc = node_in;
    const float* esrc = edge_in;
    for (int p = 0; p < 3; p++) {
        int last = (p == 2);
        k_edge_node<<<GTOT, 256, SM64>>>(esrc, ei, batch, nsrc, last);  // 3 (p=0) <- profiled
        k_node2<<<NT64, 256, SM64>>>(batch, last);                      // writes NW for p+1
        k_global<<<NG, D>>>(Wg_w, Wg_b, We_w, We_b, Wn_w, Wn_b);
        nsrc = p_node;
        esrc = p_edge;
    }
    k_readout<<<NG, D>>>(lin_w, lin_b, out);
}

// round 14
// speedup vs baseline: 1.0432x; 1.0432x over previous
#include <cuda_runtime.h>
#include <cstdint>

#define NN 50000
#define NE 600000
#define NG 64
#define D  128
#define NCLS 10
#define NT_E  (NE / 64)            // 9375 (exact)
#define NT64  ((NN + 63) / 64)     // 782

#define LDKB 272                   // bf16 tile row stride in bytes
#define LDC  132                   // float stage stride (floats)

// ---- 64-row kernel smem map (bytes), total 104448 -> 2 CTAs/SM ----
#define SO64_AH 0
#define SO64_AL 17408
#define SO64_WH 34816
#define SO64_WL 69632
#define SM64    104448

// ---------------- scratch (static device globals) ---------------------------
__device__ float g_edge[NE * D];        // updated edge features
__device__ float g_NW[NN * 2 * D];      // [node][NW1(128) | NW2(128)]
__device__ float g_tmp[NN * D];         // node @ Wn1 (produced one pass ahead)
__device__ float g_ebar[NN * D];        // per-dst edge sums (RED target)
__device__ float g_u[NG * D];
__device__ float g_uprojE[NG * D];
__device__ float g_uprojN[NG * D];
__device__ float g_gsum_node[NG * D];
__device__ float g_gsum_ebar[NG * D];
__device__ float g_nm[NG * D];          // per-pass node means (readout)
__device__ float g_em[NG * D];          // per-pass ebar means
__device__ float g_indeg[NN];
__device__ float g_cntg[NG];
__device__ uint4 g_Wimg[5][2][2048];    // bf16 [n][k] compact W images, hi/lo
                                        // 0=We1 1=We2 2=We3 3=Wn1 4=Wn2

// ---------------- helpers ------------------------------------------------
__device__ __forceinline__ uint32_t smem_to_u32(const void* p) {
    uint32_t a;
    asm("{ .reg .u64 t; cvta.to.shared.u64 t, %1; cvt.u32.u64 %0, t; }" : "=r"(a) : "l"(p));
    return a;
}
__device__ __forceinline__ uint32_t cvt2(float odd, float even) {
    uint32_t r;
    asm("cvt.rn.bf16x2.f32 %0, %1, %2;" : "=r"(r) : "f"(odd), "f"(even));
    return r;
}
__device__ __forceinline__ void split8(const float* f, uint4& hi, uint4& lo) {
    uint32_t h[4];
    float rr[8];
#pragma unroll
    for (int q = 0; q < 4; q++) {
        h[q] = cvt2(f[2 * q + 1], f[2 * q]);
        rr[2 * q]     = f[2 * q]     - __uint_as_float(h[q] << 16);
        rr[2 * q + 1] = f[2 * q + 1] - __uint_as_float(h[q] & 0xffff0000u);
    }
    hi = make_uint4(h[0], h[1], h[2], h[3]);
    lo = make_uint4(cvt2(rr[1], rr[0]), cvt2(rr[3], rr[2]), cvt2(rr[5], rr[4]), cvt2(rr[7], rr[6]));
}
__device__ __forceinline__ void split4(float4 f, uint2& hi, uint2& lo) {
    uint32_t h0 = cvt2(f.y, f.x), h1 = cvt2(f.w, f.z);
    float r0 = f.x - __uint_as_float(h0 << 16);
    float r1 = f.y - __uint_as_float(h0 & 0xffff0000u);
    float r2 = f.z - __uint_as_float(h1 << 16);
    float r3 = f.w - __uint_as_float(h1 & 0xffff0000u);
    hi = make_uint2(h0, h1);
    lo = make_uint2(cvt2(r1, r0), cvt2(r3, r2));
}
__device__ __forceinline__ void red_add_v4(float* p, float a, float b, float c, float d) {
    asm volatile("red.global.add.v4.f32 [%0], {%1,%2,%3,%4};"
                 :: "l"(p), "f"(a), "f"(b), "f"(c), "f"(d) : "memory");
}
__device__ __forceinline__ void ldm4(uint32_t addr, uint32_t r[4]) {
    asm volatile("ldmatrix.sync.aligned.m8n8.x4.shared.b16 {%0,%1,%2,%3}, [%4];"
                 : "=r"(r[0]), "=r"(r[1]), "=r"(r[2]), "=r"(r[3]) : "r"(addr));
}
__device__ __forceinline__ void mma16816(float c[4], const uint32_t a[4], uint32_t b0, uint32_t b1) {
    asm volatile("mma.sync.aligned.m16n8k16.row.col.f32.bf16.bf16.f32 "
                 "{%0,%1,%2,%3}, {%4,%5,%6,%7}, {%8,%9}, {%0,%1,%2,%3};"
                 : "+f"(c[0]), "+f"(c[1]), "+f"(c[2]), "+f"(c[3])
                 : "r"(a[0]), "r"(a[1]), "r"(a[2]), "r"(a[3]), "r"(b0), "r"(b1));
}

// ============ 64-row GEMM engine: 256 threads, 8 warps (2m x 4n) ============
__device__ __forceinline__ void mainloop64(uint32_t smb, float acc[2][4][4], int lane, int wm, int wn)
{
    uint32_t aoff = (uint32_t)((wm * 32 + (lane & 7) + ((lane >> 3) & 1) * 8) * LDKB
                               + ((lane >> 4) & 1) * 16);
    uint32_t boff = (uint32_t)((wn * 32 + (lane & 7) + ((lane >> 4) & 1) * 8) * LDKB
                               + ((lane >> 3) & 1) * 16);
    uint32_t aH = smb + SO64_AH + aoff;
    uint32_t aL = smb + SO64_AL + aoff;
    uint32_t bH = smb + SO64_WH + boff;
    uint32_t bL = smb + SO64_WL + boff;
#pragma unroll
    for (int ks = 0; ks < 8; ks++) {
        uint32_t ah[2][4], al[2][4], b[2][4];
#pragma unroll
        for (int mf = 0; mf < 2; mf++) {
            ldm4(aH + mf * 16 * LDKB + ks * 32, ah[mf]);
            ldm4(aL + mf * 16 * LDKB + ks * 32, al[mf]);
        }
#pragma unroll
        for (int np = 0; np < 2; np++) ldm4(bH + np * 16 * LDKB + ks * 32, b[np]);
#pragma unroll
        for (int mf = 0; mf < 2; mf++)
#pragma unroll
            for (int nf = 0; nf < 4; nf++)
                mma16816(acc[mf][nf], ah[mf], b[nf >> 1][(nf & 1) * 2], b[nf >> 1][(nf & 1) * 2 + 1]);
#pragma unroll
        for (int mf = 0; mf < 2; mf++)
#pragma unroll
            for (int nf = 0; nf < 4; nf++)
                mma16816(acc[mf][nf], al[mf], b[nf >> 1][(nf & 1) * 2], b[nf >> 1][(nf & 1) * 2 + 1]);
#pragma unroll
        for (int np = 0; np < 2; np++) ldm4(bL + np * 16 * LDKB + ks * 32, b[np]);
#pragma unroll
        for (int mf = 0; mf < 2; mf++)
#pragma unroll
            for (int nf = 0; nf < 4; nf++)
                mma16816(acc[mf][nf], ah[mf], b[nf >> 1][(nf & 1) * 2], b[nf >> 1][(nf & 1) * 2 + 1]);
    }
}
__device__ __forceinline__ void acc_zero64(float acc[2][4][4]) {
#pragma unroll
    for (int i = 0; i < 2; i++)
#pragma unroll
        for (int j = 0; j < 4; j++)
#pragma unroll
            for (int q = 0; q < 4; q++) acc[i][j][q] = 0.f;
}
__device__ __forceinline__ void stage64(float* smC, const float acc[2][4][4],
                                        int lane, int wm, int wn)
{
    int qr = lane >> 2, qc = (lane & 3) * 2;
#pragma unroll
    for (int mf = 0; mf < 2; mf++)
#pragma unroll
        for (int nf = 0; nf < 4; nf++) {
            float* p = smC + (wm * 32 + mf * 16 + qr) * LDC + wn * 32 + nf * 8 + qc;
            p[0] = acc[mf][nf][0];
            p[1] = acc[mf][nf][1];
            p[8 * LDC] = acc[mf][nf][2];
            p[8 * LDC + 1] = acc[mf][nf][3];
        }
}
__device__ __forceinline__ void copy_w64(char* sm, int m, int t)
{
    const uint4* sh = g_Wimg[m][0];
    const uint4* sl = g_Wimg[m][1];
#pragma unroll
    for (int i = t; i < 2048; i += 256) {
        int dst = (i >> 4) * LDKB + (i & 15) * 16;
        *(uint4*)(sm + SO64_WH + dst) = sh[i];
        *(uint4*)(sm + SO64_WL + dst) = sl[i];
    }
}
__device__ __forceinline__ void store_a64(char* sm, int r, int c8, const float* f)
{
    uint4 hi, lo; split8(f, hi, lo);
    int off = r * LDKB + c8 * 2;
    *(uint4*)(sm + SO64_AH + off) = hi;
    *(uint4*)(sm + SO64_AL + off) = lo;
}

// ---------------- k_setup: wprep + uproj(from u_in) + zero/copy ---------------
__global__ void k_setup(const float* __restrict__ u_in,
                        const float* __restrict__ We_w, const float* __restrict__ We_b,
                        const float* __restrict__ Wn_w, const float* __restrict__ Wn_b)
{
    int b = blockIdx.x, t = threadIdx.x;
    if (b < 5) {
        const float* W = (b == 0) ? We_w
                       : (b == 1) ? We_w + D * D
                       : (b == 2) ? We_w + 2 * D * D
                       : (b == 3) ? Wn_w
                                  : Wn_w + D * D;
        uint4* ih = g_Wimg[b][0];
        uint4* il = g_Wimg[b][1];
        for (int g = t; g < 2048; g += 256) {
            int n = g >> 4, c8 = (g & 15) << 3;
            float f[8];
#pragma unroll
            for (int j = 0; j < 8; j++) f[j] = W[(c8 + j) * D + n];
            uint4 hi, lo;
            split8(f, hi, lo);
            ih[g] = hi;
            il[g] = lo;
        }
    } else if (b < 69) {
        int g = b - 5;
        __shared__ float us[D];
        if (t < D) us[t] = u_in[g * D + t];
        __syncthreads();
        if (t < D) {
            int j = t;
            float aE = We_b[j], aN = Wn_b[j];
#pragma unroll 4
            for (int k = 0; k < D; k++) {
                float uv = us[k];
                aE = fmaf(uv, We_w[(3 * D + k) * D + j], aE);
                aN = fmaf(uv, Wn_w[(2 * D + k) * D + j], aN);
            }
            g_uprojE[g * D + j] = aE;
            g_uprojN[g * D + j] = aN;
            g_u[g * D + j] = us[j];
        }
    } else {
        int z = b - 69;
        int idx = z * 256 + t;
        int stride = 256 * 256;
        for (int x = idx; x < NN * D / 4; x += stride)
            ((float4*)g_ebar)[x] = make_float4(0.f, 0.f, 0.f, 0.f);
        for (int x = idx; x < NN; x += stride) g_indeg[x] = 0.f;
        if (idx < NG) g_cntg[idx] = 0.f;
        if (idx < NG * D) { g_gsum_node[idx] = 0.f; g_gsum_ebar[idx] = 0.f; }
    }
}
__global__ void k_hist(const int* __restrict__ ei, const int* __restrict__ batch)
{
    int i = blockIdx.x * blockDim.x + threadIdx.x;
    if (i < NE) atomicAdd(&g_indeg[ei[NE + i]], 1.f);
    if (i < NN) atomicAdd(&g_cntg[batch[i]], 1.f);
}

// -------- k_proj (once): NW1|NW2 = node_in @ [We1|We2], g_tmp = node_in @ Wn1 --
__global__ void __launch_bounds__(256, 2) k_proj(const float* __restrict__ Nsrc)
{
    extern __shared__ char sm[];
    uint32_t smb = smem_to_u32(sm);
    int t = threadIdx.x, lane = t & 31, wid = t >> 5;
    int wm = wid >> 2, wn = wid & 3;
    int n0 = blockIdx.x * 64;

#pragma unroll
    for (int u = 0; u < 4; u++) {
        int g = t + u * 256;
        int r = g >> 4, c8 = (g & 15) << 3;
        int n = n0 + r;
        float f[8] = {0, 0, 0, 0, 0, 0, 0, 0};
        if (n < NN) { *(float4*)f = *(const float4*)(Nsrc + (size_t)n * D + c8);
                      *(float4*)(f + 4) = *(const float4*)(Nsrc + (size_t)n * D + c8 + 4); }
        store_a64(sm, r, c8, f);
    }
    const int wsel[3] = {0, 1, 3};    // We1, We2, Wn1
#pragma unroll
    for (int h = 0; h < 3; h++) {
        copy_w64(sm, wsel[h], t);
        __syncthreads();
        float acc[2][4][4];
        acc_zero64(acc);
        mainloop64(smb, acc, lane, wm, wn);
        __syncthreads();
        stage64((float*)(sm + SO64_WH), acc, lane, wm, wn);
        __syncthreads();
#pragma unroll
        for (int rr = 0; rr < 8; rr++) {
            int r = wid * 8 + rr;
            int n = n0 + r;
            if (n < NN) {
                float4 v = *(const float4*)((const float*)(sm + SO64_WH) + r * LDC + lane * 4);
                float* dst = (h == 0) ? g_NW + (size_t)n * 256
                           : (h == 1) ? g_NW + (size_t)n * 256 + 128
                                      : g_tmp + (size_t)n * D;
                *(float4*)(dst + lane * 4) = v;
            }
        }
        __syncthreads();
    }
}

// ---------------- k_edge: relu(e@We3 + NW1[src] + NW2[dst] + uprojE) ----------
__global__ void __launch_bounds__(256, 2) k_edge_tc(const float* __restrict__ Eattr,
                                                    const int* __restrict__ ei,
                                                    const int* __restrict__ batch,
                                                    int last)
{
    extern __shared__ char sm[];
    uint32_t smb = smem_to_u32(sm);
    int t = threadIdx.x, lane = t & 31, wid = t >> 5;
    int wm = wid >> 2, wn = wid & 3;

    copy_w64(sm, 2, t);          // We3
    int r0 = t >> 4, c8v = (t & 15) << 3;
    float4 pf[8];
    int tile = blockIdx.x;
    if (tile < NT_E) {
        const float* base = Eattr + (size_t)(tile * 64) * D;
#pragma unroll
        for (int u = 0; u < 4; u++) {
            const float* p = base + (size_t)(r0 + u * 16) * D + c8v;
            pf[u * 2]     = *(const float4*)p;
            pf[u * 2 + 1] = *(const float4*)(p + 4);
        }
    }
    __syncthreads();

    for (; tile < NT_E; tile += gridDim.x) {
        int e0 = tile * 64;
#pragma unroll
        for (int u = 0; u < 4; u++) {
            float f[8];
            *(float4*)f       = pf[u * 2];
            *(float4*)(f + 4) = pf[u * 2 + 1];
            store_a64(sm, r0 + u * 16, c8v, f);
        }
        __syncthreads();
        float acc[2][4][4];
        acc_zero64(acc);
        mainloop64(smb, acc, lane, wm, wn);
        __syncthreads();
        stage64((float*)sm, acc, lane, wm, wn);
        // prefetch next tile while epilogue runs
        int nxt = tile + gridDim.x;
        if (nxt < NT_E) {
            const float* base = Eattr + (size_t)(nxt * 64) * D;
#pragma unroll
            for (int u = 0; u < 4; u++) {
                const float* p = base + (size_t)(r0 + u * 16) * D + c8v;
                pf[u * 2]     = *(const float4*)p;
                pf[u * 2 + 1] = *(const float4*)(p + 4);
            }
        }
        __syncthreads();
#pragma unroll
        for (int rr = 0; rr < 8; rr++) {
            int r = wid * 8 + rr;
            int e = e0 + r;
            int sN = ei[e], dN = ei[NE + e], gb = batch[sN];
            float4 c = *(const float4*)((const float*)sm + r * LDC + lane * 4);
            float4 a = *(const float4*)(g_NW + (size_t)sN * 256 + lane * 4);
            float4 b = *(const float4*)(g_NW + (size_t)dN * 256 + 128 + lane * 4);
            float4 u = *(const float4*)(g_uprojE + (size_t)gb * D + lane * 4);
            float y0 = fmaxf(c.x + a.x + b.x + u.x, 0.f);
            float y1 = fmaxf(c.y + a.y + b.y + u.y, 0.f);
            float y2 = fmaxf(c.z + a.z + b.z + u.z, 0.f);
            float y3 = fmaxf(c.w + a.w + b.w + u.w, 0.f);
            if (!last) *(float4*)(g_edge + (size_t)e * D + lane * 4) = make_float4(y0, y1, y2, y3);
            red_add_v4(g_ebar + (size_t)dN * D + lane * 4, y0, y1, y2, y3);
        }
        __syncthreads();
    }
}

// ---- k_node: y = relu(ebar@Wn2 + g_tmp + uprojN); NW1|NW2|g_tmp' = y@[We1|We2|Wn1]
__global__ void __launch_bounds__(256, 2) k_node(const int* __restrict__ batch, int last)
{
    extern __shared__ char sm[];
    uint32_t smb = smem_to_u32(sm);
    int t = threadIdx.x, lane = t & 31, wid = t >> 5;
    int wm = wid >> 2, wn = wid & 3;
    int n0 = blockIdx.x * 64;
    float* smS = (float*)(sm + SO64_WH);    // stage region (W dead when used)

    // A = ebar*inv_deg (zero in place, gsum_ebar RED), W = Wn2
    copy_w64(sm, 4, t);
    const float4 z4 = make_float4(0.f, 0.f, 0.f, 0.f);
#pragma unroll
    for (int u = 0; u < 4; u++) {
        int g = t + u * 256;
        int r = g >> 4, c8 = (g & 15) << 3;
        int n = n0 + r;
        float f[8] = {0, 0, 0, 0, 0, 0, 0, 0};
        if (n < NN) {
            float inv = 1.f / fmaxf(g_indeg[n], 1.f);
            float4 v0 = *(const float4*)(g_ebar + (size_t)n * D + c8);
            float4 v1 = *(const float4*)(g_ebar + (size_t)n * D + c8 + 4);
            *(float4*)(g_ebar + (size_t)n * D + c8)     = z4;
            *(float4*)(g_ebar + (size_t)n * D + c8 + 4) = z4;
            f[0] = v0.x * inv; f[1] = v0.y * inv; f[2] = v0.z * inv; f[3] = v0.w * inv;
            f[4] = v1.x * inv; f[5] = v1.y * inv; f[6] = v1.z * inv; f[7] = v1.w * inv;
            float* pg = g_gsum_ebar + (size_t)batch[n] * D + c8;
            red_add_v4(pg,     f[0], f[1], f[2], f[3]);
            red_add_v4(pg + 4, f[4], f[5], f[6], f[7]);
        }
        store_a64(sm, r, c8, f);
    }
    __syncthreads();

    float acc[2][4][4];
    acc_zero64(acc);
    mainloop64(smb, acc, lane, wm, wn);     // ebar @ Wn2
    __syncthreads();
    stage64(smS, acc, lane, wm, wn);        // over W region (dead after mainloop)
    __syncthreads();

    // epilogue: y = relu(stage + g_tmp + uprojN); gsum RED; re-split y into A
#pragma unroll
    for (int rr = 0; rr < 8; rr++) {
        int r = wid * 8 + rr;
        int n = n0 + r;
        if (n < NN) {
            int gb = batch[n];
            float4 c = *(const float4*)(smS + r * LDC + lane * 4);
            float4 w = *(const float4*)(g_tmp + (size_t)n * D + lane * 4);
            float4 u = *(const float4*)(g_uprojN + (size_t)gb * D + lane * 4);
            float4 y = make_float4(fmaxf(c.x + w.x + u.x, 0.f), fmaxf(c.y + w.y + u.y, 0.f),
                                   fmaxf(c.z + w.z + u.z, 0.f), fmaxf(c.w + w.w + u.w, 0.f));
            red_add_v4(g_gsum_node + (size_t)gb * D + lane * 4, y.x, y.y, y.z, y.w);
            if (!last) {
                uint2 hi, lo;
                split4(y, hi, lo);
                int off = r * LDKB + lane * 8;
                *(uint2*)(sm + SO64_AH + off) = hi;
                *(uint2*)(sm + SO64_AL + off) = lo;
            }
        } else if (!last) {
            int off = r * LDKB + lane * 8;
            *(uint2*)(sm + SO64_AH + off) = make_uint2(0u, 0u);
            *(uint2*)(sm + SO64_AL + off) = make_uint2(0u, 0u);
        }
    }

    // projections for next pass: NW1|NW2 = y@[We1|We2], g_tmp = y@Wn1
    if (!last) {
        const int wsel[3] = {0, 1, 3};
#pragma unroll
        for (int h = 0; h < 3; h++) {
            __syncthreads();                 // A ready / prev stage reads done
            copy_w64(sm, wsel[h], t);
            __syncthreads();
            float accp[2][4][4];
            acc_zero64(accp);
            mainloop64(smb, accp, lane, wm, wn);
            __syncthreads();
            stage64(smS, accp, lane, wm, wn);
            __syncthreads();
#pragma unroll
            for (int rr = 0; rr < 8; rr++) {
                int r = wid * 8 + rr;
                int n = n0 + r;
                if (n < NN) {
                    float4 v = *(const float4*)(smS + r * LDC + lane * 4);
                    float* dst = (h == 0) ? g_NW + (size_t)n * 256
                               : (h == 1) ? g_NW + (size_t)n * 256 + 128
                                          : g_tmp + (size_t)n * D;
                    *(float4*)(dst + lane * 4) = v;
                }
            }
        }
    }
}

// ---------------- global update + means store + gsum reset ---------------------
__global__ void k_global(const float* __restrict__ Wg_w, const float* __restrict__ Wg_b,
                         const float* __restrict__ We_w, const float* __restrict__ We_b,
                         const float* __restrict__ Wn_w, const float* __restrict__ Wn_b)
{
    int g = blockIdx.x, j = threadIdx.x;
    __shared__ float nm[D], em[D], uu[D], un[D];
    float inv = 1.f / fmaxf(g_cntg[g], 1.f);
    float nmv = g_gsum_node[g * D + j] * inv;
    float emv = g_gsum_ebar[g * D + j] * inv;
    nm[j] = nmv; em[j] = emv;
    uu[j] = g_u[g * D + j];
    g_nm[g * D + j] = nmv;
    g_em[g * D + j] = emv;
    g_gsum_node[g * D + j] = 0.f;
    g_gsum_ebar[g * D + j] = 0.f;
    __syncthreads();
    float acc = Wg_b[j];
#pragma unroll 4
    for (int k = 0; k < D; k++) {
        acc = fmaf(nm[k], Wg_w[k * D + j], acc);
        acc = fmaf(em[k], Wg_w[(D + k) * D + j], acc);
        acc = fmaf(uu[k], Wg_w[(2 * D + k) * D + j], acc);
    }
    float r = fmaxf(acc, 0.f);
    g_u[g * D + j] = r;
    un[j] = r;
    __syncthreads();
    float aE = We_b[j], aN = Wn_b[j];
#pragma unroll 4
    for (int k = 0; k < D; k++) {
        float uv = un[k];
        aE = fmaf(uv, We_w[(3 * D + k) * D + j], aE);
        aN = fmaf(uv, Wn_w[(2 * D + k) * D + j], aN);
    }
    g_uprojE[g * D + j] = aE;
    g_uprojN[g * D + j] = aN;
}

__global__ void k_readout(const float* __restrict__ lin_w, const float* __restrict__ lin_b,
                          float* __restrict__ out)
{
    int g = blockIdx.x, t = threadIdx.x;
    __shared__ float pooled[3 * D];
    pooled[t]         = g_nm[g * D + t];
    pooled[D + t]     = g_em[g * D + t];
    pooled[2 * D + t] = g_u[g * D + t];
    __syncthreads();
    if (t < NCLS) {
        float acc = lin_b[t];
#pragma unroll 4
        for (int k = 0; k < 3 * D; k++) acc = fmaf(pooled[k], lin_w[k * NCLS + t], acc);
        out[g * NCLS + t] = acc;
    }
}

// ---------------- host launcher ----------------------------------------------
extern "C" void kernel_launch(void* const* d_in, const int* in_sizes, int n_in,
                              void* d_out, int out_size)
{
    const float* node_in = (const float*)d_in[0];
    const float* edge_in = (const float*)d_in[1];
    const float* u_in    = (const float*)d_in[2];
    const int*   ei      = (const int*)d_in[3];
    const int*   batch   = (const int*)d_in[4];
    const float* We_w = (const float*)d_in[5];
    const float* We_b = (const float*)d_in[6];
    const float* Wn_w = (const float*)d_in[7];
    const float* Wn_b = (const float*)d_in[8];
    const float* Wg_w = (const float*)d_in[9];
    const float* Wg_b = (const float*)d_in[10];
    const float* lin_w = (const float*)d_in[11];
    const float* lin_b = (const float*)d_in[12];
    float* out = (float*)d_out;

    float* p_edge = nullptr;
    cudaGetSymbolAddress((void**)&p_edge, g_edge);

    cudaFuncSetAttribute(k_proj,    cudaFuncAttributeMaxDynamicSharedMemorySize, SM64);
    cudaFuncSetAttribute(k_edge_tc, cudaFuncAttributeMaxDynamicSharedMemorySize, SM64);
    cudaFuncSetAttribute(k_node,    cudaFuncAttributeMaxDynamicSharedMemorySize, SM64);

    int nsm = 148;
    cudaDeviceGetAttribute(&nsm, cudaDevAttrMultiProcessorCount, 0);
    int gp = 2 * nsm;   // persistent grid for edge kernel

    k_setup<<<325, 256>>>(u_in, We_w, We_b, Wn_w, Wn_b);   // 0
    k_hist<<<(NE + 255) / 256, 256>>>(ei, batch);          // 1
    k_proj<<<NT64, 256, SM64>>>(node_in);                  // 2 (once)

    const float* esrc = edge_in;
    for (int p = 0; p < 3; p++) {
        int last = (p == 2);
        k_edge_tc<<<gp, 256, SM64>>>(esrc, ei, batch, last);      // 3 (p=0) <- profiled
        k_node<<<NT64, 256, SM64>>>(batch, last);                 // NW + g_tmp for p+1
        k_global<<<NG, D>>>(Wg_w, Wg_b, We_w, We_b, Wn_w, Wn_b);
        esrc = p_edge;
    }
    k_readout<<<NG, D>>>(lin_w, lin_b, out);
}

// round 15
// speedup vs baseline: 1.1501x; 1.1025x over previous
#include <cuda_runtime.h>
#include <cstdint>

#define NN 50000
#define NE 600000
#define NG 64
#define D  128
#define NCLS 10
#define NT_E  (NE / 64)            // 9375 (exact)
#define NT64  ((NN + 63) / 64)     // 782

#define LDKB 272                   // bf16 tile row stride in bytes
#define LDC  132                   // float stage stride (floats)

// ---- 64-row kernel smem map (bytes), total 104448 -> 2 CTAs/SM ----
#define SO64_AH 0
#define SO64_AL 17408
#define SO64_WH 34816
#define SO64_WL 69632
#define SM64    104448

// ---------------- scratch (static device globals) ---------------------------
__device__ float g_edge[NE * D];        // updated edge features
__device__ float g_node[NN * D];
__device__ uint32_t g_NWb[NN * 128];    // bf16x2 NW table: [node][NW1(64 u32)|NW2(64 u32)]
__device__ float g_ebar[NN * D];        // per-dst edge sums (RED target)
__device__ float g_u[NG * D];
__device__ float g_uprojE[NG * D];
__device__ float g_uprojN[NG * D];
__device__ float g_gsum_node[NG * D];
__device__ float g_gsum_ebar[NG * D];
__device__ float g_nm[NG * D];          // per-pass node means (readout)
__device__ float g_em[NG * D];          // per-pass ebar means
__device__ float g_indeg[NN];
__device__ float g_cntg[NG];
__device__ uint4 g_Wimg[5][2][2048];    // bf16 [n][k] compact W images, hi/lo

// ---------------- helpers ------------------------------------------------
__device__ __forceinline__ uint32_t smem_to_u32(const void* p) {
    uint32_t a;
    asm("{ .reg .u64 t; cvta.to.shared.u64 t, %1; cvt.u32.u64 %0, t; }" : "=r"(a) : "l"(p));
    return a;
}
__device__ __forceinline__ uint32_t cvt2(float odd, float even) {  // u32 = {hi=odd, lo=even}
    uint32_t r;
    asm("cvt.rn.bf16x2.f32 %0, %1, %2;" : "=r"(r) : "f"(odd), "f"(even));
    return r;
}
__device__ __forceinline__ float2 bf2f(uint32_t u) {
    float2 v;
    v.x = __uint_as_float(u << 16);
    v.y = __uint_as_float(u & 0xffff0000u);
    return v;
}
__device__ __forceinline__ void split8(const float* f, uint4& hi, uint4& lo) {
    uint32_t h[4];
    float rr[8];
#pragma unroll
    for (int q = 0; q < 4; q++) {
        h[q] = cvt2(f[2 * q + 1], f[2 * q]);
        rr[2 * q]     = f[2 * q]     - __uint_as_float(h[q] << 16);
        rr[2 * q + 1] = f[2 * q + 1] - __uint_as_float(h[q] & 0xffff0000u);
    }
    hi = make_uint4(h[0], h[1], h[2], h[3]);
    lo = make_uint4(cvt2(rr[1], rr[0]), cvt2(rr[3], rr[2]), cvt2(rr[5], rr[4]), cvt2(rr[7], rr[6]));
}
__device__ __forceinline__ void split4(float4 f, uint2& hi, uint2& lo) {
    uint32_t h0 = cvt2(f.y, f.x), h1 = cvt2(f.w, f.z);
    float r0 = f.x - __uint_as_float(h0 << 16);
    float r1 = f.y - __uint_as_float(h0 & 0xffff0000u);
    float r2 = f.z - __uint_as_float(h1 << 16);
    float r3 = f.w - __uint_as_float(h1 & 0xffff0000u);
    hi = make_uint2(h0, h1);
    lo = make_uint2(cvt2(r1, r0), cvt2(r3, r2));
}
__device__ __forceinline__ void red_add_v4(float* p, float a, float b, float c, float d) {
    asm volatile("red.global.add.v4.f32 [%0], {%1,%2,%3,%4};"
                 :: "l"(p), "f"(a), "f"(b), "f"(c), "f"(d) : "memory");
}
__device__ __forceinline__ void ldm4(uint32_t addr, uint32_t r[4]) {
    asm volatile("ldmatrix.sync.aligned.m8n8.x4.shared.b16 {%0,%1,%2,%3}, [%4];"
                 : "=r"(r[0]), "=r"(r[1]), "=r"(r[2]), "=r"(r[3]) : "r"(addr));
}
__device__ __forceinline__ void mma16816(float c[4], const uint32_t a[4], uint32_t b0, uint32_t b1) {
    asm volatile("mma.sync.aligned.m16n8k16.row.col.f32.bf16.bf16.f32 "
                 "{%0,%1,%2,%3}, {%4,%5,%6,%7}, {%8,%9}, {%0,%1,%2,%3};"
                 : "+f"(c[0]), "+f"(c[1]), "+f"(c[2]), "+f"(c[3])
                 : "r"(a[0]), "r"(a[1]), "r"(a[2]), "r"(a[3]), "r"(b0), "r"(b1));
}

// ============ 64-row GEMM engine: 256 threads, 8 warps (2m x 4n) ============
__device__ __forceinline__ void mainloop64(uint32_t smb, float acc[2][4][4], int lane, int wm, int wn)
{
    uint32_t aoff = (uint32_t)((wm * 32 + (lane & 7) + ((lane >> 3) & 1) * 8) * LDKB
                               + ((lane >> 4) & 1) * 16);
    uint32_t boff = (uint32_t)((wn * 32 + (lane & 7) + ((lane >> 4) & 1) * 8) * LDKB
                               + ((lane >> 3) & 1) * 16);
    uint32_t aH = smb + SO64_AH + aoff;
    uint32_t aL = smb + SO64_AL + aoff;
    uint32_t bH = smb + SO64_WH + boff;
    uint32_t bL = smb + SO64_WL + boff;
#pragma unroll
    for (int ks = 0; ks < 8; ks++) {
        uint32_t ah[2][4], al[2][4], b[2][4];
#pragma unroll
        for (int mf = 0; mf < 2; mf++) {
            ldm4(aH + mf * 16 * LDKB + ks * 32, ah[mf]);
            ldm4(aL + mf * 16 * LDKB + ks * 32, al[mf]);
        }
#pragma unroll
        for (int np = 0; np < 2; np++) ldm4(bH + np * 16 * LDKB + ks * 32, b[np]);
#pragma unroll
        for (int mf = 0; mf < 2; mf++)
#pragma unroll
            for (int nf = 0; nf < 4; nf++)
                mma16816(acc[mf][nf], ah[mf], b[nf >> 1][(nf & 1) * 2], b[nf >> 1][(nf & 1) * 2 + 1]);
#pragma unroll
        for (int mf = 0; mf < 2; mf++)
#pragma unroll
            for (int nf = 0; nf < 4; nf++)
                mma16816(acc[mf][nf], al[mf], b[nf >> 1][(nf & 1) * 2], b[nf >> 1][(nf & 1) * 2 + 1]);
#pragma unroll
        for (int np = 0; np < 2; np++) ldm4(bL + np * 16 * LDKB + ks * 32, b[np]);
#pragma unroll
        for (int mf = 0; mf < 2; mf++)
#pragma unroll
            for (int nf = 0; nf < 4; nf++)
                mma16816(acc[mf][nf], ah[mf], b[nf >> 1][(nf & 1) * 2], b[nf >> 1][(nf & 1) * 2 + 1]);
    }
}
__device__ __forceinline__ void acc_zero64(float acc[2][4][4]) {
#pragma unroll
    for (int i = 0; i < 2; i++)
#pragma unroll
        for (int j = 0; j < 4; j++)
#pragma unroll
            for (int q = 0; q < 4; q++) acc[i][j][q] = 0.f;
}
__device__ __forceinline__ void stage64(float* smC, const float acc[2][4][4],
                                        int lane, int wm, int wn)
{
    int qr = lane >> 2, qc = (lane & 3) * 2;
#pragma unroll
    for (int mf = 0; mf < 2; mf++)
#pragma unroll
        for (int nf = 0; nf < 4; nf++) {
            float* p = smC + (wm * 32 + mf * 16 + qr) * LDC + wn * 32 + nf * 8 + qc;
            p[0] = acc[mf][nf][0];
            p[1] = acc[mf][nf][1];
            p[8 * LDC] = acc[mf][nf][2];
            p[8 * LDC + 1] = acc[mf][nf][3];
        }
}
__device__ __forceinline__ void copy_w64(char* sm, int m, int t)
{
    const uint4* sh = g_Wimg[m][0];
    const uint4* sl = g_Wimg[m][1];
#pragma unroll
    for (int i = t; i < 2048; i += 256) {
        int dst = (i >> 4) * LDKB + (i & 15) * 16;
        *(uint4*)(sm + SO64_WH + dst) = sh[i];
        *(uint4*)(sm + SO64_WL + dst) = sl[i];
    }
}
__device__ __forceinline__ void store_a64(char* sm, int r, int c8, const float* f)
{
    uint4 hi, lo; split8(f, hi, lo);
    int off = r * LDKB + c8 * 2;
    *(uint4*)(sm + SO64_AH + off) = hi;
    *(uint4*)(sm + SO64_AL + off) = lo;
}

// ---------------- k_setup: wprep + uproj(from u_in) + zero/copy ---------------
__global__ void k_setup(const float* __restrict__ u_in,
                        const float* __restrict__ We_w, const float* __restrict__ We_b,
                        const float* __restrict__ Wn_w, const float* __restrict__ Wn_b)
{
    int b = blockIdx.x, t = threadIdx.x;
    if (b < 5) {
        const float* W = (b == 0) ? We_w
                       : (b == 1) ? We_w + D * D
                       : (b == 2) ? We_w + 2 * D * D
                       : (b == 3) ? Wn_w
                                  : Wn_w + D * D;
        uint4* ih = g_Wimg[b][0];
        uint4* il = g_Wimg[b][1];
        for (int g = t; g < 2048; g += 256) {
            int n = g >> 4, c8 = (g & 15) << 3;
            float f[8];
#pragma unroll
            for (int j = 0; j < 8; j++) f[j] = W[(c8 + j) * D + n];
            uint4 hi, lo;
            split8(f, hi, lo);
            ih[g] = hi;
            il[g] = lo;
        }
    } else if (b < 69) {
        int g = b - 5;
        __shared__ float us[D];
        if (t < D) us[t] = u_in[g * D + t];
        __syncthreads();
        if (t < D) {
            int j = t;
            float aE = We_b[j], aN = Wn_b[j];
#pragma unroll 4
            for (int k = 0; k < D; k++) {
                float uv = us[k];
                aE = fmaf(uv, We_w[(3 * D + k) * D + j], aE);
                aN = fmaf(uv, Wn_w[(2 * D + k) * D + j], aN);
            }
            g_uprojE[g * D + j] = aE;
            g_uprojN[g * D + j] = aN;
            g_u[g * D + j] = us[j];
        }
    } else {
        int z = b - 69;
        int idx = z * 256 + t;
        int stride = 256 * 256;
        for (int x = idx; x < NN * D / 4; x += stride)
            ((float4*)g_ebar)[x] = make_float4(0.f, 0.f, 0.f, 0.f);
        for (int x = idx; x < NN; x += stride) g_indeg[x] = 0.f;
        if (idx < NG) g_cntg[idx] = 0.f;
        if (idx < NG * D) { g_gsum_node[idx] = 0.f; g_gsum_ebar[idx] = 0.f; }
    }
}
__global__ void k_hist(const int* __restrict__ ei, const int* __restrict__ batch)
{
    int i = blockIdx.x * blockDim.x + threadIdx.x;
    if (i < NE) atomicAdd(&g_indeg[ei[NE + i]], 1.f);
    if (i < NN) atomicAdd(&g_cntg[batch[i]], 1.f);
}

// ---------------- k_proj (pass 0 only): NW = node_in @ [We1|We2] (bf16 store) --
__global__ void __launch_bounds__(256, 2) k_proj(const float* __restrict__ Nsrc)
{
    extern __shared__ char sm[];
    uint32_t smb = smem_to_u32(sm);
    int t = threadIdx.x, lane = t & 31, wid = t >> 5;
    int wm = wid >> 2, wn = wid & 3;
    int n0 = blockIdx.x * 64;

#pragma unroll
    for (int u = 0; u < 4; u++) {
        int g = t + u * 256;
        int r = g >> 4, c8 = (g & 15) << 3;
        int n = n0 + r;
        float f[8] = {0, 0, 0, 0, 0, 0, 0, 0};
        if (n < NN) { *(float4*)f = *(const float4*)(Nsrc + (size_t)n * D + c8);
                      *(float4*)(f + 4) = *(const float4*)(Nsrc + (size_t)n * D + c8 + 4); }
        store_a64(sm, r, c8, f);
    }
#pragma unroll
    for (int half = 0; half < 2; half++) {
        copy_w64(sm, half, t);                // We1 then We2
        __syncthreads();
        float acc[2][4][4];
        acc_zero64(acc);
        mainloop64(smb, acc, lane, wm, wn);
        __syncthreads();
        stage64((float*)(sm + SO64_WH), acc, lane, wm, wn);
        __syncthreads();
#pragma unroll
        for (int rr = 0; rr < 8; rr++) {
            int r = wid * 8 + rr;
            int n = n0 + r;
            if (n < NN) {
                float4 v = *(const float4*)((const float*)(sm + SO64_WH) + r * LDC + lane * 4);
                uint2 h = make_uint2(cvt2(v.y, v.x), cvt2(v.w, v.z));
                *(uint2*)(g_NWb + (size_t)n * 128 + half * 64 + lane * 2) = h;
            }
        }
        __syncthreads();
    }
}

// ---------------- k_edge: relu(e@We3 + NW1[src] + NW2[dst] + uprojE) ----------
__global__ void __launch_bounds__(256, 2) k_edge_tc(const float* __restrict__ Eattr,
                                                    const int* __restrict__ ei,
                                                    const int* __restrict__ batch,
                                                    int last)
{
    extern __shared__ char sm[];
    uint32_t smb = smem_to_u32(sm);
    int t = threadIdx.x, lane = t & 31, wid = t >> 5;
    int wm = wid >> 2, wn = wid & 3;

    copy_w64(sm, 2, t);          // We3
    int r0 = t >> 4, c8v = (t & 15) << 3;
    float4 pf[8];
    int tile = blockIdx.x;
    if (tile < NT_E) {
        const float* base = Eattr + (size_t)(tile * 64) * D;
#pragma unroll
        for (int u = 0; u < 4; u++) {
            const float* p = base + (size_t)(r0 + u * 16) * D + c8v;
            pf[u * 2]     = *(const float4*)p;
            pf[u * 2 + 1] = *(const float4*)(p + 4);
        }
    }
    __syncthreads();

    for (; tile < NT_E; tile += gridDim.x) {
        int e0 = tile * 64;
#pragma unroll
        for (int u = 0; u < 4; u++) {
            float f[8];
            *(float4*)f       = pf[u * 2];
            *(float4*)(f + 4) = pf[u * 2 + 1];
            store_a64(sm, r0 + u * 16, c8v, f);
        }
        __syncthreads();
        float acc[2][4][4];
        acc_zero64(acc);
        mainloop64(smb, acc, lane, wm, wn);
        __syncthreads();
        stage64((float*)sm, acc, lane, wm, wn);
        // prefetch next tile while epilogue runs
        int nxt = tile + gridDim.x;
        if (nxt < NT_E) {
            const float* base = Eattr + (size_t)(nxt * 64) * D;
#pragma unroll
            for (int u = 0; u < 4; u++) {
                const float* p = base + (size_t)(r0 + u * 16) * D + c8v;
                pf[u * 2]     = *(const float4*)p;
                pf[u * 2 + 1] = *(const float4*)(p + 4);
            }
        }
        __syncthreads();
#pragma unroll
        for (int rr = 0; rr < 8; rr++) {
            int r = wid * 8 + rr;
            int e = e0 + r;
            int sN = ei[e], dN = ei[NE + e], gb = batch[sN];
            float4 c = *(const float4*)((const float*)sm + r * LDC + lane * 4);
            uint2 ua = *(const uint2*)(g_NWb + (size_t)sN * 128 + lane * 2);
            uint2 ub = *(const uint2*)(g_NWb + (size_t)dN * 128 + 64 + lane * 2);
            float4 u = *(const float4*)(g_uprojE + (size_t)gb * D + lane * 4);
            float2 a01 = bf2f(ua.x), a23 = bf2f(ua.y);
            float2 b01 = bf2f(ub.x), b23 = bf2f(ub.y);
            float y0 = fmaxf(c.x + a01.x + b01.x + u.x, 0.f);
            float y1 = fmaxf(c.y + a01.y + b01.y + u.y, 0.f);
            float y2 = fmaxf(c.z + a23.x + b23.x + u.z, 0.f);
            float y3 = fmaxf(c.w + a23.y + b23.y + u.w, 0.f);
            if (!last) *(float4*)(g_edge + (size_t)e * D + lane * 4) = make_float4(y0, y1, y2, y3);
            red_add_v4(g_ebar + (size_t)dN * D + lane * 4, y0, y1, y2, y3);
        }
        __syncthreads();
    }
}

// ---- k_node (fused): y = relu(ebar@Wn2 + node@Wn1 + uprojN); then NW = y@[We1|We2]
__global__ void __launch_bounds__(256, 2) k_node(const float* __restrict__ Nsrc,
                                                 const int* __restrict__ batch, int last)
{
    extern __shared__ char sm[];
    uint32_t smb = smem_to_u32(sm);
    int t = threadIdx.x, lane = t & 31, wid = t >> 5;
    int wm = wid >> 2, wn = wid & 3;
    int n0 = blockIdx.x * 64;
    float* smS = (float*)(sm + SO64_WH);    // stage region (W dead when used)

    // phase 1: A = ebar*inv_deg (zero in place, gsum_ebar RED), W = Wn2
    copy_w64(sm, 4, t);
    const float4 z4 = make_float4(0.f, 0.f, 0.f, 0.f);
#pragma unroll
    for (int u = 0; u < 4; u++) {
        int g = t + u * 256;
        int r = g >> 4, c8 = (g & 15) << 3;
        int n = n0 + r;
        float f[8] = {0, 0, 0, 0, 0, 0, 0, 0};
        if (n < NN) {
            float inv = 1.f / fmaxf(g_indeg[n], 1.f);
            float4 v0 = *(const float4*)(g_ebar + (size_t)n * D + c8);
            float4 v1 = *(const float4*)(g_ebar + (size_t)n * D + c8 + 4);
            *(float4*)(g_ebar + (size_t)n * D + c8)     = z4;
            *(float4*)(g_ebar + (size_t)n * D + c8 + 4) = z4;
            f[0] = v0.x * inv; f[1] = v0.y * inv; f[2] = v0.z * inv; f[3] = v0.w * inv;
            f[4] = v1.x * inv; f[5] = v1.y * inv; f[6] = v1.z * inv; f[7] = v1.w * inv;
            float* pg = g_gsum_ebar + (size_t)batch[n] * D + c8;
            red_add_v4(pg,     f[0], f[1], f[2], f[3]);
            red_add_v4(pg + 4, f[4], f[5], f[6], f[7]);
        }
        store_a64(sm, r, c8, f);
    }
    __syncthreads();

    float acc[2][4][4];
    acc_zero64(acc);
    mainloop64(smb, acc, lane, wm, wn);     // ebar @ Wn2
    __syncthreads();

    // phase 2: A = node features, W = Wn1
    copy_w64(sm, 3, t);
#pragma unroll
    for (int u = 0; u < 4; u++) {
        int g = t + u * 256;
        int r = g >> 4, c8 = (g & 15) << 3;
        int n = n0 + r;
        float f[8] = {0, 0, 0, 0, 0, 0, 0, 0};
        if (n < NN) { *(float4*)f = *(const float4*)(Nsrc + (size_t)n * D + c8);
                      *(float4*)(f + 4) = *(const float4*)(Nsrc + (size_t)n * D + c8 + 4); }
        store_a64(sm, r, c8, f);
    }
    __syncthreads();
    mainloop64(smb, acc, lane, wm, wn);     // + node @ Wn1
    __syncthreads();
    stage64(smS, acc, lane, wm, wn);        // over W region (dead)
    __syncthreads();

    // epilogue: y = relu(c+u); store node/gsum; re-split y into A for NW GEMMs
#pragma unroll
    for (int rr = 0; rr < 8; rr++) {
        int r = wid * 8 + rr;
        int n = n0 + r;
        if (n < NN) {
            int gb = batch[n];
            float4 c = *(const float4*)(smS + r * LDC + lane * 4);
            float4 u = *(const float4*)(g_uprojN + (size_t)gb * D + lane * 4);
            float4 y = make_float4(fmaxf(c.x + u.x, 0.f), fmaxf(c.y + u.y, 0.f),
                                   fmaxf(c.z + u.z, 0.f), fmaxf(c.w + u.w, 0.f));
            red_add_v4(g_gsum_node + (size_t)gb * D + lane * 4, y.x, y.y, y.z, y.w);
            if (!last) {
                *(float4*)(g_node + (size_t)n * D + lane * 4) = y;
                uint2 hi, lo;
                split4(y, hi, lo);
                int off = r * LDKB + lane * 8;
                *(uint2*)(sm + SO64_AH + off) = hi;
                *(uint2*)(sm + SO64_AL + off) = lo;
            }
        } else if (!last) {
            int off = r * LDKB + lane * 8;
            *(uint2*)(sm + SO64_AH + off) = make_uint2(0u, 0u);
            *(uint2*)(sm + SO64_AL + off) = make_uint2(0u, 0u);
        }
    }

    // NW for next pass: NW1|NW2 = y @ [We1|We2]  (bf16 store)
    if (!last) {
#pragma unroll
        for (int half = 0; half < 2; half++) {
            __syncthreads();                 // A ready / NW-write of prev half done
            copy_w64(sm, half, t);           // We1 then We2
            __syncthreads();
            float accp[2][4][4];
            acc_zero64(accp);
            mainloop64(smb, accp, lane, wm, wn);
            __syncthreads();
            stage64(smS, accp, lane, wm, wn);
            __syncthreads();
#pragma unroll
            for (int rr = 0; rr < 8; rr++) {
                int r = wid * 8 + rr;
                int n = n0 + r;
                if (n < NN) {
                    float4 v = *(const float4*)(smS + r * LDC + lane * 4);
                    uint2 h = make_uint2(cvt2(v.y, v.x), cvt2(v.w, v.z));
                    *(uint2*)(g_NWb + (size_t)n * 128 + half * 64 + lane * 2) = h;
                }
            }
        }
    }
}

// ---------------- global update + means store + gsum reset ---------------------
__global__ void k_global(const float* __restrict__ Wg_w, const float* __restrict__ Wg_b,
                         const float* __restrict__ We_w, const float* __restrict__ We_b,
                         const float* __restrict__ Wn_w, const float* __restrict__ Wn_b)
{
    int g = blockIdx.x, j = threadIdx.x;
    __shared__ float nm[D], em[D], uu[D], un[D];
    float inv = 1.f / fmaxf(g_cntg[g], 1.f);
    float nmv = g_gsum_node[g * D + j] * inv;
    float emv = g_gsum_ebar[g * D + j] * inv;
    nm[j] = nmv; em[j] = emv;
    uu[j] = g_u[g * D + j];
    g_nm[g * D + j] = nmv;
    g_em[g * D + j] = emv;
    g_gsum_node[g * D + j] = 0.f;
    g_gsum_ebar[g * D + j] = 0.f;
    __syncthreads();
    float acc = Wg_b[j];
#pragma unroll 4
    for (int k = 0; k < D; k++) {
        acc = fmaf(nm[k], Wg_w[k * D + j], acc);
        acc = fmaf(em[k], Wg_w[(D + k) * D + j], acc);
        acc = fmaf(uu[k], Wg_w[(2 * D + k) * D + j], acc);
    }
    float r = fmaxf(acc, 0.f);
    g_u[g * D + j] = r;
    un[j] = r;
    __syncthreads();
    float aE = We_b[j], aN = Wn_b[j];
#pragma unroll 4
    for (int k = 0; k < D; k++) {
        float uv = un[k];
        aE = fmaf(uv, We_w[(3 * D + k) * D + j], aE);
        aN = fmaf(uv, Wn_w[(2 * D + k) * D + j], aN);
    }
    g_uprojE[g * D + j] = aE;
    g_uprojN[g * D + j] = aN;
}

__global__ void k_readout(const float* __restrict__ lin_w, const float* __restrict__ lin_b,
                          float* __restrict__ out)
{
    int g = blockIdx.x, t = threadIdx.x;
    __shared__ float pooled[3 * D];
    pooled[t]         = g_nm[g * D + t];
    pooled[D + t]     = g_em[g * D + t];
    pooled[2 * D + t] = g_u[g * D + t];
    __syncthreads();
    if (t < NCLS) {
        float acc = lin_b[t];
#pragma unroll 4
        for (int k = 0; k < 3 * D; k++) acc = fmaf(pooled[k], lin_w[k * NCLS + t], acc);
        out[g * NCLS + t] = acc;
    }
}

// ---------------- host launcher ----------------------------------------------
extern "C" void kernel_launch(void* const* d_in, const int* in_sizes, int n_in,
                              void* d_out, int out_size)
{
    const float* node_in = (const float*)d_in[0];
    const float* edge_in = (const float*)d_in[1];
    const float* u_in    = (const float*)d_in[2];
    const int*   ei      = (const int*)d_in[3];
    const int*   batch   = (const int*)d_in[4];
    const float* We_w = (const float*)d_in[5];
    const float* We_b = (const float*)d_in[6];
    const float* Wn_w = (const float*)d_in[7];
    const float* Wn_b = (const float*)d_in[8];
    const float* Wg_w = (const float*)d_in[9];
    const float* Wg_b = (const float*)d_in[10];
    const float* lin_w = (const float*)d_in[11];
    const float* lin_b = (const float*)d_in[12];
    float* out = (float*)d_out;

    float *p_node = nullptr, *p_edge = nullptr;
    cudaGetSymbolAddress((void**)&p_node, g_node);
    cudaGetSymbolAddress((void**)&p_edge, g_edge);

    cudaFuncSetAttribute(k_proj,    cudaFuncAttributeMaxDynamicSharedMemorySize, SM64);
    cudaFuncSetAttribute(k_edge_tc, cudaFuncAttributeMaxDynamicSharedMemorySize, SM64);
    cudaFuncSetAttribute(k_node,    cudaFuncAttributeMaxDynamicSharedMemorySize, SM64);

    int nsm = 148;
    cudaDeviceGetAttribute(&nsm, cudaDevAttrMultiProcessorCount, 0);
    int gp = 2 * nsm;   // persistent grid for edge kernel

    k_setup<<<325, 256>>>(u_in, We_w, We_b, Wn_w, Wn_b);   // 0
    k_hist<<<(NE + 255) / 256, 256>>>(ei, batch);          // 1
    k_proj<<<NT64, 256, SM64>>>(node_in);                  // 2 (once)

    const float* nsrc = node_in;
    const float* esrc = edge_in;
    for (int p = 0; p < 3; p++) {
        int last = (p == 2);
        k_edge_tc<<<gp, 256, SM64>>>(esrc, ei, batch, last);      // 3 (p=0) <- profiled
        k_node<<<NT64, 256, SM64>>>(nsrc, batch, last);           // writes NW for pass p+1
        k_global<<<NG, D>>>(Wg_w, Wg_b, We_w, We_b, Wn_w, Wn_b);
        nsrc = p_node;
        esrc = p_edge;
    }
    k_readout<<<NG, D>>>(lin_w, lin_b, out);
}

// round 16
// speedup vs baseline: 1.1827x; 1.0284x over previous
#include <cuda_runtime.h>
#include <cstdint>

#define NN 50000
#define NE 600000
#define NG 64
#define D  128
#define NCLS 10
#define NT_E  (NE / 64)            // 9375 (exact)
#define NT64  ((NN + 63) / 64)     // 782

#define LDKB 272                   // bf16 tile row stride in bytes
#define LDC  132                   // float stage stride (floats)

// ---- 64-row kernel smem map (bytes), total 104448 -> 2 CTAs/SM ----
#define SO64_AH 0
#define SO64_AL 17408
#define SO64_WH 34816
#define SO64_WL 69632
#define SM64    104448

// ---------------- scratch (static device globals) ---------------------------
__device__ float g_edge[NE * D];        // updated edge features
__device__ float g_node[NN * D];
__device__ uint32_t g_NWb[NN * 128];    // bf16x2 NW table: [node][NW1(64 u32)|NW2(64 u32)]
__device__ float g_ebar[NN * D];        // per-dst edge sums (RED target)
__device__ float g_u[NG * D];
__device__ float g_uprojE[NG * D];
__device__ float g_uprojN[NG * D];
__device__ float g_gsum_node[NG * D];
__device__ float g_gsum_ebar[NG * D];
__device__ float g_nm[NG * D];          // per-pass node means (readout)
__device__ float g_em[NG * D];          // per-pass ebar means
__device__ float g_indeg[NN];
__device__ float g_cntg[NG];
__device__ uint4 g_Wimg[5][2][2048];    // bf16 [n][k] compact W images, hi/lo

// ---------------- helpers ------------------------------------------------
__device__ __forceinline__ uint32_t smem_to_u32(const void* p) {
    uint32_t a;
    asm("{ .reg .u64 t; cvta.to.shared.u64 t, %1; cvt.u32.u64 %0, t; }" : "=r"(a) : "l"(p));
    return a;
}
__device__ __forceinline__ uint32_t cvt2(float odd, float even) {  // u32 = {hi=odd, lo=even}
    uint32_t r;
    asm("cvt.rn.bf16x2.f32 %0, %1, %2;" : "=r"(r) : "f"(odd), "f"(even));
    return r;
}
__device__ __forceinline__ float2 bf2f(uint32_t u) {
    float2 v;
    v.x = __uint_as_float(u << 16);
    v.y = __uint_as_float(u & 0xffff0000u);
    return v;
}
__device__ __forceinline__ void split8(const float* f, uint4& hi, uint4& lo) {
    uint32_t h[4];
    float rr[8];
#pragma unroll
    for (int q = 0; q < 4; q++) {
        h[q] = cvt2(f[2 * q + 1], f[2 * q]);
        rr[2 * q]     = f[2 * q]     - __uint_as_float(h[q] << 16);
        rr[2 * q + 1] = f[2 * q + 1] - __uint_as_float(h[q] & 0xffff0000u);
    }
    hi = make_uint4(h[0], h[1], h[2], h[3]);
    lo = make_uint4(cvt2(rr[1], rr[0]), cvt2(rr[3], rr[2]), cvt2(rr[5], rr[4]), cvt2(rr[7], rr[6]));
}
__device__ __forceinline__ void split4(float4 f, uint2& hi, uint2& lo) {
    uint32_t h0 = cvt2(f.y, f.x), h1 = cvt2(f.w, f.z);
    float r0 = f.x - __uint_as_float(h0 << 16);
    float r1 = f.y - __uint_as_float(h0 & 0xffff0000u);
    float r2 = f.z - __uint_as_float(h1 << 16);
    float r3 = f.w - __uint_as_float(h1 & 0xffff0000u);
    hi = make_uint2(h0, h1);
    lo = make_uint2(cvt2(r1, r0), cvt2(r3, r2));
}
__device__ __forceinline__ void red_add_v4(float* p, float a, float b, float c, float d) {
    asm volatile("red.global.add.v4.f32 [%0], {%1,%2,%3,%4};"
                 :: "l"(p), "f"(a), "f"(b), "f"(c), "f"(d) : "memory");
}
__device__ __forceinline__ void ldm4(uint32_t addr, uint32_t r[4]) {
    asm volatile("ldmatrix.sync.aligned.m8n8.x4.shared.b16 {%0,%1,%2,%3}, [%4];"
                 : "=r"(r[0]), "=r"(r[1]), "=r"(r[2]), "=r"(r[3]) : "r"(addr));
}
__device__ __forceinline__ void mma16816(float c[4], const uint32_t a[4], uint32_t b0, uint32_t b1) {
    asm volatile("mma.sync.aligned.m16n8k16.row.col.f32.bf16.bf16.f32 "
                 "{%0,%1,%2,%3}, {%4,%5,%6,%7}, {%8,%9}, {%0,%1,%2,%3};"
                 : "+f"(c[0]), "+f"(c[1]), "+f"(c[2]), "+f"(c[3])
                 : "r"(a[0]), "r"(a[1]), "r"(a[2]), "r"(a[3]), "r"(b0), "r"(b1));
}

// ============ 64-row GEMM engine: 256 threads, 8 warps (2m x 4n) ============
__device__ __forceinline__ void mainloop64(uint32_t smb, float acc[2][4][4], int lane, int wm, int wn)
{
    uint32_t aoff = (uint32_t)((wm * 32 + (lane & 7) + ((lane >> 3) & 1) * 8) * LDKB
                               + ((lane >> 4) & 1) * 16);
    uint32_t boff = (uint32_t)((wn * 32 + (lane & 7) + ((lane >> 4) & 1) * 8) * LDKB
                               + ((lane >> 3) & 1) * 16);
    uint32_t aH = smb + SO64_AH + aoff;
    uint32_t aL = smb + SO64_AL + aoff;
    uint32_t bH = smb + SO64_WH + boff;
    uint32_t bL = smb + SO64_WL + boff;
#pragma unroll
    for (int ks = 0; ks < 8; ks++) {
        uint32_t ah[2][4], al[2][4], b[2][4];
#pragma unroll
        for (int mf = 0; mf < 2; mf++) {
            ldm4(aH + mf * 16 * LDKB + ks * 32, ah[mf]);
            ldm4(aL + mf * 16 * LDKB + ks * 32, al[mf]);
        }
#pragma unroll
        for (int np = 0; np < 2; np++) ldm4(bH + np * 16 * LDKB + ks * 32, b[np]);
#pragma unroll
        for (int mf = 0; mf < 2; mf++)
#pragma unroll
            for (int nf = 0; nf < 4; nf++)
                mma16816(acc[mf][nf], ah[mf], b[nf >> 1][(nf & 1) * 2], b[nf >> 1][(nf & 1) * 2 + 1]);
#pragma unroll
        for (int mf = 0; mf < 2; mf++)
#pragma unroll
            for (int nf = 0; nf < 4; nf++)
                mma16816(acc[mf][nf], al[mf], b[nf >> 1][(nf & 1) * 2], b[nf >> 1][(nf & 1) * 2 + 1]);
#pragma unroll
        for (int np = 0; np < 2; np++) ldm4(bL + np * 16 * LDKB + ks * 32, b[np]);
#pragma unroll
        for (int mf = 0; mf < 2; mf++)
#pragma unroll
            for (int nf = 0; nf < 4; nf++)
                mma16816(acc[mf][nf], ah[mf], b[nf >> 1][(nf & 1) * 2], b[nf >> 1][(nf & 1) * 2 + 1]);
    }
}
__device__ __forceinline__ void acc_zero64(float acc[2][4][4]) {
#pragma unroll
    for (int i = 0; i < 2; i++)
#pragma unroll
        for (int j = 0; j < 4; j++)
#pragma unroll
            for (int q = 0; q < 4; q++) acc[i][j][q] = 0.f;
}
__device__ __forceinline__ void stage64(float* smC, const float acc[2][4][4],
                                        int lane, int wm, int wn)
{
    int qr = lane >> 2, qc = (lane & 3) * 2;
#pragma unroll
    for (int mf = 0; mf < 2; mf++)
#pragma unroll
        for (int nf = 0; nf < 4; nf++) {
            float* p = smC + (wm * 32 + mf * 16 + qr) * LDC + wn * 32 + nf * 8 + qc;
            p[0] = acc[mf][nf][0];
            p[1] = acc[mf][nf][1];
            p[8 * LDC] = acc[mf][nf][2];
            p[8 * LDC + 1] = acc[mf][nf][3];
        }
}
__device__ __forceinline__ void copy_w64(char* sm, int m, int t)
{
    const uint4* sh = g_Wimg[m][0];
    const uint4* sl = g_Wimg[m][1];
#pragma unroll
    for (int i = t; i < 2048; i += 256) {
        int dst = (i >> 4) * LDKB + (i & 15) * 16;
        *(uint4*)(sm + SO64_WH + dst) = sh[i];
        *(uint4*)(sm + SO64_WL + dst) = sl[i];
    }
}
__device__ __forceinline__ void store_a64(char* sm, int r, int c8, const float* f)
{
    uint4 hi, lo; split8(f, hi, lo);
    int off = r * LDKB + c8 * 2;
    *(uint4*)(sm + SO64_AH + off) = hi;
    *(uint4*)(sm + SO64_AL + off) = lo;
}

// ---------------- k_setup: wprep + uproj(from u_in) + zero/copy ---------------
__global__ void k_setup(const float* __restrict__ u_in,
                        const float* __restrict__ We_w, const float* __restrict__ We_b,
                        const float* __restrict__ Wn_w, const float* __restrict__ Wn_b)
{
    int b = blockIdx.x, t = threadIdx.x;
    if (b < 5) {
        const float* W = (b == 0) ? We_w
                       : (b == 1) ? We_w + D * D
                       : (b == 2) ? We_w + 2 * D * D
                       : (b == 3) ? Wn_w
                                  : Wn_w + D * D;
        uint4* ih = g_Wimg[b][0];
        uint4* il = g_Wimg[b][1];
        for (int g = t; g < 2048; g += 256) {
            int n = g >> 4, c8 = (g & 15) << 3;
            float f[8];
#pragma unroll
            for (int j = 0; j < 8; j++) f[j] = W[(c8 + j) * D + n];
            uint4 hi, lo;
            split8(f, hi, lo);
            ih[g] = hi;
            il[g] = lo;
        }
    } else if (b < 69) {
        int g = b - 5;
        __shared__ float us[D];
        if (t < D) us[t] = u_in[g * D + t];
        __syncthreads();
        if (t < D) {
            int j = t;
            float aE = We_b[j], aN = Wn_b[j];
#pragma unroll 4
            for (int k = 0; k < D; k++) {
                float uv = us[k];
                aE = fmaf(uv, We_w[(3 * D + k) * D + j], aE);
                aN = fmaf(uv, Wn_w[(2 * D + k) * D + j], aN);
            }
            g_uprojE[g * D + j] = aE;
            g_uprojN[g * D + j] = aN;
            g_u[g * D + j] = us[j];
        }
    } else {
        int z = b - 69;
        int idx = z * 256 + t;
        int stride = 256 * 256;
        for (int x = idx; x < NN * D / 4; x += stride)
            ((float4*)g_ebar)[x] = make_float4(0.f, 0.f, 0.f, 0.f);
        for (int x = idx; x < NN; x += stride) g_indeg[x] = 0.f;
        if (idx < NG) g_cntg[idx] = 0.f;
        if (idx < NG * D) { g_gsum_node[idx] = 0.f; g_gsum_ebar[idx] = 0.f; }
    }
}
__global__ void k_hist(const int* __restrict__ ei, const int* __restrict__ batch)
{
    int i = blockIdx.x * blockDim.x + threadIdx.x;
    if (i < NE) atomicAdd(&g_indeg[ei[NE + i]], 1.f);
    if (i < NN) atomicAdd(&g_cntg[batch[i]], 1.f);
}

// ---------------- k_proj (pass 0 only): NW = node_in @ [We1|We2] (bf16 store) --
__global__ void __launch_bounds__(256, 2) k_proj(const float* __restrict__ Nsrc)
{
    extern __shared__ char sm[];
    uint32_t smb = smem_to_u32(sm);
    int t = threadIdx.x, lane = t & 31, wid = t >> 5;
    int wm = wid >> 2, wn = wid & 3;
    int n0 = blockIdx.x * 64;

#pragma unroll
    for (int u = 0; u < 4; u++) {
        int g = t + u * 256;
        int r = g >> 4, c8 = (g & 15) << 3;
        int n = n0 + r;
        float f[8] = {0, 0, 0, 0, 0, 0, 0, 0};
        if (n < NN) { *(float4*)f = *(const float4*)(Nsrc + (size_t)n * D + c8);
                      *(float4*)(f + 4) = *(const float4*)(Nsrc + (size_t)n * D + c8 + 4); }
        store_a64(sm, r, c8, f);
    }
#pragma unroll
    for (int half = 0; half < 2; half++) {
        copy_w64(sm, half, t);                // We1 then We2
        __syncthreads();
        float acc[2][4][4];
        acc_zero64(acc);
        mainloop64(smb, acc, lane, wm, wn);
        __syncthreads();
        stage64((float*)(sm + SO64_WH), acc, lane, wm, wn);
        __syncthreads();
#pragma unroll
        for (int rr = 0; rr < 8; rr++) {
            int r = wid * 8 + rr;
            int n = n0 + r;
            if (n < NN) {
                float4 v = *(const float4*)((const float*)(sm + SO64_WH) + r * LDC + lane * 4);
                uint2 h = make_uint2(cvt2(v.y, v.x), cvt2(v.w, v.z));
                *(uint2*)(g_NWb + (size_t)n * 128 + half * 64 + lane * 2) = h;
            }
        }
        __syncthreads();
    }
}

// ---------------- k_edge: relu(e@We3 + NW1[src] + NW2[dst] + uprojE) ----------
__global__ void __launch_bounds__(256, 2) k_edge_tc(const float* __restrict__ Eattr,
                                                    const int* __restrict__ ei,
                                                    const int* __restrict__ batch,
                                                    int last)
{
    extern __shared__ char sm[];
    uint32_t smb = smem_to_u32(sm);
    int t = threadIdx.x, lane = t & 31, wid = t >> 5;
    int wm = wid >> 2, wn = wid & 3;

    copy_w64(sm, 2, t);          // We3
    int r0 = t >> 4, c8v = (t & 15) << 3;
    float4 pf[8];
    int tile = blockIdx.x;
    if (tile < NT_E) {
        const float* base = Eattr + (size_t)(tile * 64) * D;
#pragma unroll
        for (int u = 0; u < 4; u++) {
            const float* p = base + (size_t)(r0 + u * 16) * D + c8v;
            pf[u * 2]     = *(const float4*)p;
            pf[u * 2 + 1] = *(const float4*)(p + 4);
        }
    }
    __syncthreads();

    for (; tile < NT_E; tile += gridDim.x) {
        int e0 = tile * 64;
#pragma unroll
        for (int u = 0; u < 4; u++) {
            float f[8];
            *(float4*)f       = pf[u * 2];
            *(float4*)(f + 4) = pf[u * 2 + 1];
            store_a64(sm, r0 + u * 16, c8v, f);
        }
        __syncthreads();
        float acc[2][4][4];
        acc_zero64(acc);
        mainloop64(smb, acc, lane, wm, wn);
        __syncthreads();
        stage64((float*)sm, acc, lane, wm, wn);
        // prefetch next tile while epilogue runs
        int nxt = tile + gridDim.x;
        if (nxt < NT_E) {
            const float* base = Eattr + (size_t)(nxt * 64) * D;
#pragma unroll
            for (int u = 0; u < 4; u++) {
                const float* p = base + (size_t)(r0 + u * 16) * D + c8v;
                pf[u * 2]     = *(const float4*)p;
                pf[u * 2 + 1] = *(const float4*)(p + 4);
            }
        }
        __syncthreads();
#pragma unroll
        for (int rr = 0; rr < 8; rr++) {
            int r = wid * 8 + rr;
            int e = e0 + r;
            int sN = ei[e], dN = ei[NE + e], gb = batch[sN];
            float4 c = *(const float4*)((const float*)sm + r * LDC + lane * 4);
            uint2 ua = *(const uint2*)(g_NWb + (size_t)sN * 128 + lane * 2);
            uint2 ub = *(const uint2*)(g_NWb + (size_t)dN * 128 + 64 + lane * 2);
            float4 u = *(const float4*)(g_uprojE + (size_t)gb * D + lane * 4);
            float2 a01 = bf2f(ua.x), a23 = bf2f(ua.y);
            float2 b01 = bf2f(ub.x), b23 = bf2f(ub.y);
            float y0 = fmaxf(c.x + a01.x + b01.x + u.x, 0.f);
            float y1 = fmaxf(c.y + a01.y + b01.y + u.y, 0.f);
            float y2 = fmaxf(c.z + a23.x + b23.x + u.z, 0.f);
            float y3 = fmaxf(c.w + a23.y + b23.y + u.w, 0.f);
            if (!last) *(float4*)(g_edge + (size_t)e * D + lane * 4) = make_float4(y0, y1, y2, y3);
            red_add_v4(g_ebar + (size_t)dN * D + lane * 4, y0, y1, y2, y3);
        }
        __syncthreads();
    }
}

// ---- k_node (fused): y = relu(ebar@Wn2 + node@Wn1 + uprojN); then NW = y@[We1|We2]
__global__ void __launch_bounds__(256, 2) k_node(const float* __restrict__ Nsrc,
                                                 const int* __restrict__ batch, int last)
{
    extern __shared__ char sm[];
    uint32_t smb = smem_to_u32(sm);
    int t = threadIdx.x, lane = t & 31, wid = t >> 5;
    int wm = wid >> 2, wn = wid & 3;
    int n0 = blockIdx.x * 64;
    float* smS = (float*)(sm + SO64_WH);    // stage region (W dead when used)

    // phase 1: A = ebar*inv_deg (zero in place, gsum_ebar RED), W = Wn2
    copy_w64(sm, 4, t);
    const float4 z4 = make_float4(0.f, 0.f, 0.f, 0.f);
#pragma unroll
    for (int u = 0; u < 4; u++) {
        int g = t + u * 256;
        int r = g >> 4, c8 = (g & 15) << 3;
        int n = n0 + r;
        float f[8] = {0, 0, 0, 0, 0, 0, 0, 0};
        if (n < NN) {
            float inv = 1.f / fmaxf(g_indeg[n], 1.f);
            float4 v0 = *(const float4*)(g_ebar + (size_t)n * D + c8);
            float4 v1 = *(const float4*)(g_ebar + (size_t)n * D + c8 + 4);
            *(float4*)(g_ebar + (size_t)n * D + c8)     = z4;
            *(float4*)(g_ebar + (size_t)n * D + c8 + 4) = z4;
            f[0] = v0.x * inv; f[1] = v0.y * inv; f[2] = v0.z * inv; f[3] = v0.w * inv;
            f[4] = v1.x * inv; f[5] = v1.y * inv; f[6] = v1.z * inv; f[7] = v1.w * inv;
            float* pg = g_gsum_ebar + (size_t)batch[n] * D + c8;
            red_add_v4(pg,     f[0], f[1], f[2], f[3]);
            red_add_v4(pg + 4, f[4], f[5], f[6], f[7]);
        }
        store_a64(sm, r, c8, f);
    }
    __syncthreads();

    float acc[2][4][4];
    acc_zero64(acc);
    mainloop64(smb, acc, lane, wm, wn);     // ebar @ Wn2
    __syncthreads();

    // phase 2: A = node features, W = Wn1
    copy_w64(sm, 3, t);
#pragma unroll
    for (int u = 0; u < 4; u++) {
        int g = t + u * 256;
        int r = g >> 4, c8 = (g & 15) << 3;
        int n = n0 + r;
        float f[8] = {0, 0, 0, 0, 0, 0, 0, 0};
        if (n < NN) { *(float4*)f = *(const float4*)(Nsrc + (size_t)n * D + c8);
                      *(float4*)(f + 4) = *(const float4*)(Nsrc + (size_t)n * D + c8 + 4); }
        store_a64(sm, r, c8, f);
    }
    __syncthreads();
    mainloop64(smb, acc, lane, wm, wn);     // + node @ Wn1
    __syncthreads();
    stage64(smS, acc, lane, wm, wn);        // over W region (dead)
    __syncthreads();

    // epilogue: y = relu(c+u); store node/gsum; re-split y into A for NW GEMMs
#pragma unroll
    for (int rr = 0; rr < 8; rr++) {
        int r = wid * 8 + rr;
        int n = n0 + r;
        if (n < NN) {
            int gb = batch[n];
            float4 c = *(const float4*)(smS + r * LDC + lane * 4);
            float4 u = *(const float4*)(g_uprojN + (size_t)gb * D + lane * 4);
            float4 y = make_float4(fmaxf(c.x + u.x, 0.f), fmaxf(c.y + u.y, 0.f),
                                   fmaxf(c.z + u.z, 0.f), fmaxf(c.w + u.w, 0.f));
            red_add_v4(g_gsum_node + (size_t)gb * D + lane * 4, y.x, y.y, y.z, y.w);
            if (!last) {
                *(float4*)(g_node + (size_t)n * D + lane * 4) = y;
                uint2 hi, lo;
                split4(y, hi, lo);
                int off = r * LDKB + lane * 8;
                *(uint2*)(sm + SO64_AH + off) = hi;
                *(uint2*)(sm + SO64_AL + off) = lo;
            }
        } else if (!last) {
            int off = r * LDKB + lane * 8;
            *(uint2*)(sm + SO64_AH + off) = make_uint2(0u, 0u);
            *(uint2*)(sm + SO64_AL + off) = make_uint2(0u, 0u);
        }
    }

    // NW for next pass: NW1|NW2 = y @ [We1|We2]  (bf16 store)
    if (!last) {
#pragma unroll
        for (int half = 0; half < 2; half++) {
            __syncthreads();                 // A ready / NW-write of prev half done
            copy_w64(sm, half, t);           // We1 then We2
            __syncthreads();
            float accp[2][4][4];
            acc_zero64(accp);
            mainloop64(smb, accp, lane, wm, wn);
            __syncthreads();
            stage64(smS, accp, lane, wm, wn);
            __syncthreads();
#pragma unroll
            for (int rr = 0; rr < 8; rr++) {
                int r = wid * 8 + rr;
                int n = n0 + r;
                if (n < NN) {
                    float4 v = *(const float4*)(smS + r * LDC + lane * 4);
                    uint2 h = make_uint2(cvt2(v.y, v.x), cvt2(v.w, v.z));
                    *(uint2*)(g_NWb + (size_t)n * 128 + half * 64 + lane * 2) = h;
                }
            }
        }
    }
}

// ------- k_global: 512 threads, k-loop split 4 ways + smem reduction ----------
__global__ void __launch_bounds__(512) k_global(const float* __restrict__ Wg_w,
                                                const float* __restrict__ Wg_b,
                                                const float* __restrict__ We_w,
                                                const float* __restrict__ We_b,
                                                const float* __restrict__ Wn_w,
                                                const float* __restrict__ Wn_b,
                                                int last)
{
    int g = blockIdx.x;
    int t = threadIdx.x;
    int j = t & 127, q = t >> 7;            // q in 0..3, k-range [32q, 32q+32)
    __shared__ float nm[D], em[D], uu[D], un[D];
    __shared__ float red[4][D], redE[4][D], redN[4][D];

    if (q == 0) {
        float inv = 1.f / fmaxf(g_cntg[g], 1.f);
        float nmv = g_gsum_node[g * D + j] * inv;
        float emv = g_gsum_ebar[g * D + j] * inv;
        nm[j] = nmv; em[j] = emv;
        uu[j] = g_u[g * D + j];
        g_nm[g * D + j] = nmv;
        g_em[g * D + j] = emv;
        g_gsum_node[g * D + j] = 0.f;       // reset for next pass
        g_gsum_ebar[g * D + j] = 0.f;
    }
    __syncthreads();

    float acc = 0.f;
    int k0 = q * 32;
#pragma unroll 4
    for (int k = k0; k < k0 + 32; k++) {
        acc = fmaf(nm[k], Wg_w[k * D + j], acc);
        acc = fmaf(em[k], Wg_w[(D + k) * D + j], acc);
        acc = fmaf(uu[k], Wg_w[(2 * D + k) * D + j], acc);
    }
    red[q][j] = acc;
    __syncthreads();

    if (q == 0) {
        float s = Wg_b[j] + red[0][j] + red[1][j] + red[2][j] + red[3][j];
        float r = fmaxf(s, 0.f);
        g_u[g * D + j] = r;
        un[j] = r;
    }
    if (last) return;                        // uproj values dead after final pass
    __syncthreads();

    float aE = 0.f, aN = 0.f;
#pragma unroll 4
    for (int k = k0; k < k0 + 32; k++) {
        float uv = un[k];
        aE = fmaf(uv, We_w[(3 * D + k) * D + j], aE);
        aN = fmaf(uv, Wn_w[(2 * D + k) * D + j], aN);
    }
    redE[q][j] = aE;
    redN[q][j] = aN;
    __syncthreads();

    if (q == 0) {
        g_uprojE[g * D + j] = We_b[j] + redE[0][j] + redE[1][j] + redE[2][j] + redE[3][j];
        g_uprojN[g * D + j] = Wn_b[j] + redN[0][j] + redN[1][j] + redN[2][j] + redN[3][j];
    }
}

__global__ void k_readout(const float* __restrict__ lin_w, const float* __restrict__ lin_b,
                          float* __restrict__ out)
{
    int g = blockIdx.x, t = threadIdx.x;
    __shared__ float pooled[3 * D];
    pooled[t]         = g_nm[g * D + t];
    pooled[D + t]     = g_em[g * D + t];
    pooled[2 * D + t] = g_u[g * D + t];
    __syncthreads();
    if (t < NCLS) {
        float acc = lin_b[t];
#pragma unroll 4
        for (int k = 0; k < 3 * D; k++) acc = fmaf(pooled[k], lin_w[k * NCLS + t], acc);
        out[g * NCLS + t] = acc;
    }
}

// ---------------- host launcher ----------------------------------------------
extern "C" void kernel_launch(void* const* d_in, const int* in_sizes, int n_in,
                              void* d_out, int out_size)
{
    const float* node_in = (const float*)d_in[0];
    const float* edge_in = (const float*)d_in[1];
    const float* u_in    = (const float*)d_in[2];
    const int*   ei      = (const int*)d_in[3];
    const int*   batch   = (const int*)d_in[4];
    const float* We_w = (const float*)d_in[5];
    const float* We_b = (const float*)d_in[6];
    const float* Wn_w = (const float*)d_in[7];
    const float* Wn_b = (const float*)d_in[8];
    const float* Wg_w = (const float*)d_in[9];
    const float* Wg_b = (const float*)d_in[10];
    const float* lin_w = (const float*)d_in[11];
    const float* lin_b = (const float*)d_in[12];
    float* out = (float*)d_out;

    float *p_node = nullptr, *p_edge = nullptr;
    cudaGetSymbolAddress((void**)&p_node, g_node);
    cudaGetSymbolAddress((void**)&p_edge, g_edge);

    cudaFuncSetAttribute(k_proj,    cudaFuncAttributeMaxDynamicSharedMemorySize, SM64);
    cudaFuncSetAttribute(k_edge_tc, cudaFuncAttributeMaxDynamicSharedMemorySize, SM64);
    cudaFuncSetAttribute(k_node,    cudaFuncAttributeMaxDynamicSharedMemorySize, SM64);

    int nsm = 148;
    cudaDeviceGetAttribute(&nsm, cudaDevAttrMultiProcessorCount, 0);
    int gp = 2 * nsm;   // persistent grid for edge kernel

    k_setup<<<325, 256>>>(u_in, We_w, We_b, Wn_w, Wn_b);   // 0
    k_hist<<<(NE + 255) / 256, 256>>>(ei, batch);          // 1
    k_proj<<<NT64, 256, SM64>>>(node_in);                  // 2 (once)

    const float* nsrc = node_in;
    const float* esrc = edge_in;
    for (int p = 0; p < 3; p++) {
        int last = (p == 2);
        k_edge_tc<<<gp, 256, SM64>>>(esrc, ei, batch, last);      // 3 (p=0) <- profiled
        k_node<<<NT64, 256, SM64>>>(nsrc, batch, last);           // writes NW for pass p+1
        k_global<<<NG, 512>>>(Wg_w, Wg_b, We_w, We_b, Wn_w, Wn_b, last);
        nsrc = p_node;
        esrc = p_edge;
    }
    k_readout<<<NG, D>>>(lin_w, lin_b, out);
}

// round 17
// speedup vs baseline: 1.2570x; 1.0628x over previous
#include <cuda_runtime.h>
#include <cstdint>

#define NN 50000
#define NE 600000
#define NG 64
#define D  128
#define NCLS 10
#define NT_E  (NE / 64)            // 9375 (exact)
#define NT64  ((NN + 63) / 64)     // 782

#define LDKB 272                   // bf16 tile row stride in bytes
#define LDC  132                   // float stage stride (floats)

// ---- 64-row kernel smem map (bytes), total 104448 -> 2 CTAs/SM ----
#define SO64_AH 0
#define SO64_AL 17408
#define SO64_WH 34816
#define SO64_WL 69632
#define SM64    104448

// ---------------- scratch (static device globals) ---------------------------
__device__ uint32_t g_edgeb[NE * 64];   // edge features, bf16x2 (154 MB)
__device__ float g_node[NN * D];
__device__ uint32_t g_NWb[NN * 128];    // bf16x2 NW table: [node][NW1(64)|NW2(64)]
__device__ float g_ebar[NN * D];        // per-dst edge sums (RED target)
__device__ float g_u[NG * D];
__device__ float g_uprojE[NG * D];
__device__ float g_uprojN[NG * D];
__device__ float g_gsum_node[NG * D];
__device__ float g_gsum_ebar[NG * D];
__device__ float g_nm[NG * D];          // per-pass node means (readout)
__device__ float g_em[NG * D];          // per-pass ebar means
__device__ float g_indeg[NN];
__device__ float g_cntg[NG];
__device__ uint4 g_Wimg[5][2][2048];    // bf16 [n][k] compact W images, hi/lo

// ---------------- helpers ------------------------------------------------
__device__ __forceinline__ uint32_t smem_to_u32(const void* p) {
    uint32_t a;
    asm("{ .reg .u64 t; cvta.to.shared.u64 t, %1; cvt.u32.u64 %0, t; }" : "=r"(a) : "l"(p));
    return a;
}
__device__ __forceinline__ uint32_t cvt2(float odd, float even) {  // u32 = {hi=odd, lo=even}
    uint32_t r;
    asm("cvt.rn.bf16x2.f32 %0, %1, %2;" : "=r"(r) : "f"(odd), "f"(even));
    return r;
}
__device__ __forceinline__ float2 bf2f(uint32_t u) {
    float2 v;
    v.x = __uint_as_float(u << 16);
    v.y = __uint_as_float(u & 0xffff0000u);
    return v;
}
__device__ __forceinline__ void split8(const float* f, uint4& hi, uint4& lo) {
    uint32_t h[4];
    float rr[8];
#pragma unroll
    for (int q = 0; q < 4; q++) {
        h[q] = cvt2(f[2 * q + 1], f[2 * q]);
        rr[2 * q]     = f[2 * q]     - __uint_as_float(h[q] << 16);
        rr[2 * q + 1] = f[2 * q + 1] - __uint_as_float(h[q] & 0xffff0000u);
    }
    hi = make_uint4(h[0], h[1], h[2], h[3]);
    lo = make_uint4(cvt2(rr[1], rr[0]), cvt2(rr[3], rr[2]), cvt2(rr[5], rr[4]), cvt2(rr[7], rr[6]));
}
__device__ __forceinline__ void split4(float4 f, uint2& hi, uint2& lo) {
    uint32_t h0 = cvt2(f.y, f.x), h1 = cvt2(f.w, f.z);
    float r0 = f.x - __uint_as_float(h0 << 16);
    float r1 = f.y - __uint_as_float(h0 & 0xffff0000u);
    float r2 = f.z - __uint_as_float(h1 << 16);
    float r3 = f.w - __uint_as_float(h1 & 0xffff0000u);
    hi = make_uint2(h0, h1);
    lo = make_uint2(cvt2(r1, r0), cvt2(r3, r2));
}
__device__ __forceinline__ void red_add_v4(float* p, float a, float b, float c, float d) {
    asm volatile("red.global.add.v4.f32 [%0], {%1,%2,%3,%4};"
                 :: "l"(p), "f"(a), "f"(b), "f"(c), "f"(d) : "memory");
}
__device__ __forceinline__ void ldm4(uint32_t addr, uint32_t r[4]) {
    asm volatile("ldmatrix.sync.aligned.m8n8.x4.shared.b16 {%0,%1,%2,%3}, [%4];"
                 : "=r"(r[0]), "=r"(r[1]), "=r"(r[2]), "=r"(r[3]) : "r"(addr));
}
__device__ __forceinline__ void mma16816(float c[4], const uint32_t a[4], uint32_t b0, uint32_t b1) {
    asm volatile("mma.sync.aligned.m16n8k16.row.col.f32.bf16.bf16.f32 "
                 "{%0,%1,%2,%3}, {%4,%5,%6,%7}, {%8,%9}, {%0,%1,%2,%3};"
                 : "+f"(c[0]), "+f"(c[1]), "+f"(c[2]), "+f"(c[3])
                 : "r"(a[0]), "r"(a[1]), "r"(a[2]), "r"(a[3]), "r"(b0), "r"(b1));
}

// ============ 64-row GEMM engine: 256 threads, 8 warps (2m x 4n) ============
// THREE: Ah*Wh + Al*Wh + Ah*Wl.  !THREE: A exact bf16 (AL tile unused).
template<bool THREE>
__device__ __forceinline__ void mainloop64(uint32_t smb, float acc[2][4][4], int lane, int wm, int wn)
{
    uint32_t aoff = (uint32_t)((wm * 32 + (lane & 7) + ((lane >> 3) & 1) * 8) * LDKB
                               + ((lane >> 4) & 1) * 16);
    uint32_t boff = (uint32_t)((wn * 32 + (lane & 7) + ((lane >> 4) & 1) * 8) * LDKB
                               + ((lane >> 3) & 1) * 16);
    uint32_t aH = smb + SO64_AH + aoff;
    uint32_t aL = smb + SO64_AL + aoff;
    uint32_t bH = smb + SO64_WH + boff;
    uint32_t bL = smb + SO64_WL + boff;
#pragma unroll
    for (int ks = 0; ks < 8; ks++) {
        uint32_t ah[2][4], al[2][4], b[2][4];
#pragma unroll
        for (int mf = 0; mf < 2; mf++) {
            ldm4(aH + mf * 16 * LDKB + ks * 32, ah[mf]);
            if (THREE) ldm4(aL + mf * 16 * LDKB + ks * 32, al[mf]);
        }
#pragma unroll
        for (int np = 0; np < 2; np++) ldm4(bH + np * 16 * LDKB + ks * 32, b[np]);
#pragma unroll
        for (int mf = 0; mf < 2; mf++)
#pragma unroll
            for (int nf = 0; nf < 4; nf++)
                mma16816(acc[mf][nf], ah[mf], b[nf >> 1][(nf & 1) * 2], b[nf >> 1][(nf & 1) * 2 + 1]);
        if (THREE) {
#pragma unroll
            for (int mf = 0; mf < 2; mf++)
#pragma unroll
                for (int nf = 0; nf < 4; nf++)
                    mma16816(acc[mf][nf], al[mf], b[nf >> 1][(nf & 1) * 2], b[nf >> 1][(nf & 1) * 2 + 1]);
        }
#pragma unroll
        for (int np = 0; np < 2; np++) ldm4(bL + np * 16 * LDKB + ks * 32, b[np]);
#pragma unroll
        for (int mf = 0; mf < 2; mf++)
#pragma unroll
            for (int nf = 0; nf < 4; nf++)
                mma16816(acc[mf][nf], ah[mf], b[nf >> 1][(nf & 1) * 2], b[nf >> 1][(nf & 1) * 2 + 1]);
    }
}
__device__ __forceinline__ void acc_zero64(float acc[2][4][4]) {
#pragma unroll
    for (int i = 0; i < 2; i++)
#pragma unroll
        for (int j = 0; j < 4; j++)
#pragma unroll
            for (int q = 0; q < 4; q++) acc[i][j][q] = 0.f;
}
__device__ __forceinline__ void stage64(float* smC, const float acc[2][4][4],
                                        int lane, int wm, int wn)
{
    int qr = lane >> 2, qc = (lane & 3) * 2;
#pragma unroll
    for (int mf = 0; mf < 2; mf++)
#pragma unroll
        for (int nf = 0; nf < 4; nf++) {
            float* p = smC + (wm * 32 + mf * 16 + qr) * LDC + wn * 32 + nf * 8 + qc;
            p[0] = acc[mf][nf][0];
            p[1] = acc[mf][nf][1];
            p[8 * LDC] = acc[mf][nf][2];
            p[8 * LDC + 1] = acc[mf][nf][3];
        }
}
__device__ __forceinline__ void copy_w64(char* sm, int m, int t)
{
    const uint4* sh = g_Wimg[m][0];
    const uint4* sl = g_Wimg[m][1];
#pragma unroll
    for (int i = t; i < 2048; i += 256) {
        int dst = (i >> 4) * LDKB + (i & 15) * 16;
        *(uint4*)(sm + SO64_WH + dst) = sh[i];
        *(uint4*)(sm + SO64_WL + dst) = sl[i];
    }
}
__device__ __forceinline__ void store_a64(char* sm, int r, int c8, const float* f)
{
    uint4 hi, lo; split8(f, hi, lo);
    int off = r * LDKB + c8 * 2;
    *(uint4*)(sm + SO64_AH + off) = hi;
    *(uint4*)(sm + SO64_AL + off) = lo;
}

// ---------------- k_setup: wprep + uproj(from u_in) + zero/copy ---------------
__global__ void k_setup(const float* __restrict__ u_in,
                        const float* __restrict__ We_w, const float* __restrict__ We_b,
                        const float* __restrict__ Wn_w, const float* __restrict__ Wn_b)
{
    int b = blockIdx.x, t = threadIdx.x;
    if (b < 5) {
        const float* W = (b == 0) ? We_w
                       : (b == 1) ? We_w + D * D
                       : (b == 2) ? We_w + 2 * D * D
                       : (b == 3) ? Wn_w
                                  : Wn_w + D * D;
        uint4* ih = g_Wimg[b][0];
        uint4* il = g_Wimg[b][1];
        for (int g = t; g < 2048; g += 256) {
            int n = g >> 4, c8 = (g & 15) << 3;
            float f[8];
#pragma unroll
            for (int j = 0; j < 8; j++) f[j] = W[(c8 + j) * D + n];
            uint4 hi, lo;
            split8(f, hi, lo);
            ih[g] = hi;
            il[g] = lo;
        }
    } else if (b < 69) {
        int g = b - 5;
        __shared__ float us[D];
        if (t < D) us[t] = u_in[g * D + t];
        __syncthreads();
        if (t < D) {
            int j = t;
            float aE = We_b[j], aN = Wn_b[j];
#pragma unroll 4
            for (int k = 0; k < D; k++) {
                float uv = us[k];
                aE = fmaf(uv, We_w[(3 * D + k) * D + j], aE);
                aN = fmaf(uv, Wn_w[(2 * D + k) * D + j], aN);
            }
            g_uprojE[g * D + j] = aE;
            g_uprojN[g * D + j] = aN;
            g_u[g * D + j] = us[j];
        }
    } else {
        int z = b - 69;
        int idx = z * 256 + t;
        int stride = 256 * 256;
        for (int x = idx; x < NN * D / 4; x += stride)
            ((float4*)g_ebar)[x] = make_float4(0.f, 0.f, 0.f, 0.f);
        for (int x = idx; x < NN; x += stride) g_indeg[x] = 0.f;
        if (idx < NG) g_cntg[idx] = 0.f;
        if (idx < NG * D) { g_gsum_node[idx] = 0.f; g_gsum_ebar[idx] = 0.f; }
    }
}
__global__ void k_hist(const int* __restrict__ ei, const int* __restrict__ batch)
{
    int i = blockIdx.x * blockDim.x + threadIdx.x;
    if (i < NE) atomicAdd(&g_indeg[ei[NE + i]], 1.f);
    if (i < NN) atomicAdd(&g_cntg[batch[i]], 1.f);
}

// ---------------- k_proj (pass 0 only): NW = node_in @ [We1|We2] (bf16 store) --
__global__ void __launch_bounds__(256, 2) k_proj(const float* __restrict__ Nsrc)
{
    extern __shared__ char sm[];
    uint32_t smb = smem_to_u32(sm);
    int t = threadIdx.x, lane = t & 31, wid = t >> 5;
    int wm = wid >> 2, wn = wid & 3;
    int n0 = blockIdx.x * 64;

#pragma unroll
    for (int u = 0; u < 4; u++) {
        int g = t + u * 256;
        int r = g >> 4, c8 = (g & 15) << 3;
        int n = n0 + r;
        float f[8] = {0, 0, 0, 0, 0, 0, 0, 0};
        if (n < NN) { *(float4*)f = *(const float4*)(Nsrc + (size_t)n * D + c8);
                      *(float4*)(f + 4) = *(const float4*)(Nsrc + (size_t)n * D + c8 + 4); }
        store_a64(sm, r, c8, f);
    }
#pragma unroll
    for (int half = 0; half < 2; half++) {
        copy_w64(sm, half, t);                // We1 then We2
        __syncthreads();
        float acc[2][4][4];
        acc_zero64(acc);
        mainloop64<true>(smb, acc, lane, wm, wn);
        __syncthreads();
        stage64((float*)(sm + SO64_WH), acc, lane, wm, wn);
        __syncthreads();
#pragma unroll
        for (int rr = 0; rr < 8; rr++) {
            int r = wid * 8 + rr;
            int n = n0 + r;
            if (n < NN) {
                float4 v = *(const float4*)((const float*)(sm + SO64_WH) + r * LDC + lane * 4);
                uint2 h = make_uint2(cvt2(v.y, v.x), cvt2(v.w, v.z));
                *(uint2*)(g_NWb + (size_t)n * 128 + half * 64 + lane * 2) = h;
            }
        }
        __syncthreads();
    }
}

// ---------------- k_edge: relu(e@We3 + NW1[src] + NW2[dst] + uprojE) ----------
// EBF=false: pass 0, A from fp32 Eattr (3-term). EBF=true: A from bf16 g_edgeb (2-term).
template<bool EBF>
__global__ void __launch_bounds__(256, 2) k_edge_tc(const float* __restrict__ Eattr,
                                                    const int* __restrict__ ei,
                                                    const int* __restrict__ batch,
                                                    int last)
{
    extern __shared__ char sm[];
    uint32_t smb = smem_to_u32(sm);
    int t = threadIdx.x, lane = t & 31, wid = t >> 5;
    int wm = wid >> 2, wn = wid & 3;

    copy_w64(sm, 2, t);          // We3
    int r0 = t >> 4, c8v = (t & 15) << 3;
    float4 pf[8];
    uint4 pfb[4];
    int tile = blockIdx.x;
    if (tile < NT_E) {
        if (EBF) {
            const uint32_t* base = g_edgeb + (size_t)(tile * 64) * 64;
#pragma unroll
            for (int u = 0; u < 4; u++)
                pfb[u] = *(const uint4*)(base + (size_t)(r0 + u * 16) * 64 + (c8v >> 1));
        } else {
            const float* base = Eattr + (size_t)(tile * 64) * D;
#pragma unroll
            for (int u = 0; u < 4; u++) {
                const float* p = base + (size_t)(r0 + u * 16) * D + c8v;
                pf[u * 2]     = *(const float4*)p;
                pf[u * 2 + 1] = *(const float4*)(p + 4);
            }
        }
    }
    __syncthreads();

    for (; tile < NT_E; tile += gridDim.x) {
        int e0 = tile * 64;
#pragma unroll
        for (int u = 0; u < 4; u++) {
            if (EBF) {
                *(uint4*)(sm + SO64_AH + (r0 + u * 16) * LDKB + c8v * 2) = pfb[u];
            } else {
                float f[8];
                *(float4*)f       = pf[u * 2];
                *(float4*)(f + 4) = pf[u * 2 + 1];
                store_a64(sm, r0 + u * 16, c8v, f);
            }
        }
        __syncthreads();
        float acc[2][4][4];
        acc_zero64(acc);
        mainloop64<!EBF>(smb, acc, lane, wm, wn);
        __syncthreads();
        stage64((float*)sm, acc, lane, wm, wn);
        // prefetch next tile while epilogue runs
        int nxt = tile + gridDim.x;
        if (nxt < NT_E) {
            if (EBF) {
                const uint32_t* base = g_edgeb + (size_t)(nxt * 64) * 64;
#pragma unroll
                for (int u = 0; u < 4; u++)
                    pfb[u] = *(const uint4*)(base + (size_t)(r0 + u * 16) * 64 + (c8v >> 1));
            } else {
                const float* base = Eattr + (size_t)(nxt * 64) * D;
#pragma unroll
                for (int u = 0; u < 4; u++) {
                    const float* p = base + (size_t)(r0 + u * 16) * D + c8v;
                    pf[u * 2]     = *(const float4*)p;
                    pf[u * 2 + 1] = *(const float4*)(p + 4);
                }
            }
        }
        __syncthreads();
#pragma unroll
        for (int rr = 0; rr < 8; rr++) {
            int r = wid * 8 + rr;
            int e = e0 + r;
            int sN = ei[e], dN = ei[NE + e], gb = batch[sN];
            float4 c = *(const float4*)((const float*)sm + r * LDC + lane * 4);
            uint2 ua = *(const uint2*)(g_NWb + (size_t)sN * 128 + lane * 2);
            uint2 ub = *(const uint2*)(g_NWb + (size_t)dN * 128 + 64 + lane * 2);
            float4 u = *(const float4*)(g_uprojE + (size_t)gb * D + lane * 4);
            float2 a01 = bf2f(ua.x), a23 = bf2f(ua.y);
            float2 b01 = bf2f(ub.x), b23 = bf2f(ub.y);
            float y0 = fmaxf(c.x + a01.x + b01.x + u.x, 0.f);
            float y1 = fmaxf(c.y + a01.y + b01.y + u.y, 0.f);
            float y2 = fmaxf(c.z + a23.x + b23.x + u.z, 0.f);
            float y3 = fmaxf(c.w + a23.y + b23.y + u.w, 0.f);
            if (!last) {
                uint2 h = make_uint2(cvt2(y1, y0), cvt2(y3, y2));
                *(uint2*)(g_edgeb + (size_t)e * 64 + lane * 2) = h;
            }
            red_add_v4(g_ebar + (size_t)dN * D + lane * 4, y0, y1, y2, y3);
        }
        __syncthreads();
    }
}

// ---- k_node (fused): y = relu(ebar@Wn2 + node@Wn1 + uprojN); then NW = y@[We1|We2]
__global__ void __launch_bounds__(256, 2) k_node(const float* __restrict__ Nsrc,
                                                 const int* __restrict__ batch, int last)
{
    extern __shared__ char sm[];
    uint32_t smb = smem_to_u32(sm);
    int t = threadIdx.x, lane = t & 31, wid = t >> 5;
    int wm = wid >> 2, wn = wid & 3;
    int n0 = blockIdx.x * 64;
    float* smS = (float*)(sm + SO64_WH);    // stage region (W dead when used)

    // phase 1: A = ebar*inv_deg (zero in place, gsum_ebar RED), W = Wn2
    copy_w64(sm, 4, t);
    const float4 z4 = make_float4(0.f, 0.f, 0.f, 0.f);
#pragma unroll
    for (int u = 0; u < 4; u++) {
        int g = t + u * 256;
        int r = g >> 4, c8 = (g & 15) << 3;
        int n = n0 + r;
        float f[8] = {0, 0, 0, 0, 0, 0, 0, 0};
        if (n < NN) {
            float inv = 1.f / fmaxf(g_indeg[n], 1.f);
            float4 v0 = *(const float4*)(g_ebar + (size_t)n * D + c8);
            float4 v1 = *(const float4*)(g_ebar + (size_t)n * D + c8 + 4);
            *(float4*)(g_ebar + (size_t)n * D + c8)     = z4;
            *(float4*)(g_ebar + (size_t)n * D + c8 + 4) = z4;
            f[0] = v0.x * inv; f[1] = v0.y * inv; f[2] = v0.z * inv; f[3] = v0.w * inv;
            f[4] = v1.x * inv; f[5] = v1.y * inv; f[6] = v1.z * inv; f[7] = v1.w * inv;
            float* pg = g_gsum_ebar + (size_t)batch[n] * D + c8;
            red_add_v4(pg,     f[0], f[1], f[2], f[3]);
            red_add_v4(pg + 4, f[4], f[5], f[6], f[7]);
        }
        store_a64(sm, r, c8, f);
    }
    __syncthreads();

    float acc[2][4][4];
    acc_zero64(acc);
    mainloop64<true>(smb, acc, lane, wm, wn);     // ebar @ Wn2
    __syncthreads();

    // phase 2: A = node features, W = Wn1
    copy_w64(sm, 3, t);
#pragma unroll
    for (int u = 0; u < 4; u++) {
        int g = t + u * 256;
        int r = g >> 4, c8 = (g & 15) << 3;
        int n = n0 + r;
        float f[8] = {0, 0, 0, 0, 0, 0, 0, 0};
        if (n < NN) { *(float4*)f = *(const float4*)(Nsrc + (size_t)n * D + c8);
                      *(float4*)(f + 4) = *(const float4*)(Nsrc + (size_t)n * D + c8 + 4); }
        store_a64(sm, r, c8, f);
    }
    __syncthreads();
    mainloop64<true>(smb, acc, lane, wm, wn);     // + node @ Wn1
    __syncthreads();
    stage64(smS, acc, lane, wm, wn);              // over W region (dead)
    __syncthreads();

    // epilogue: y = relu(c+u); store node/gsum; re-split y into A for NW GEMMs
#pragma unroll
    for (int rr = 0; rr < 8; rr++) {
        int r = wid * 8 + rr;
        int n = n0 + r;
        if (n < NN) {
            int gb = batch[n];
            float4 c = *(const float4*)(smS + r * LDC + lane * 4);
            float4 u = *(const float4*)(g_uprojN + (size_t)gb * D + lane * 4);
            float4 y = make_float4(fmaxf(c.x + u.x, 0.f), fmaxf(c.y + u.y, 0.f),
                                   fmaxf(c.z + u.z, 0.f), fmaxf(c.w + u.w, 0.f));
            red_add_v4(g_gsum_node + (size_t)gb * D + lane * 4, y.x, y.y, y.z, y.w);
            if (!last) {
                *(float4*)(g_node + (size_t)n * D + lane * 4) = y;
                uint2 hi, lo;
                split4(y, hi, lo);
                int off = r * LDKB + lane * 8;
                *(uint2*)(sm + SO64_AH + off) = hi;
                *(uint2*)(sm + SO64_AL + off) = lo;
            }
        } else if (!last) {
            int off = r * LDKB + lane * 8;
            *(uint2*)(sm + SO64_AH + off) = make_uint2(0u, 0u);
            *(uint2*)(sm + SO64_AL + off) = make_uint2(0u, 0u);
        }
    }

    // NW for next pass: NW1|NW2 = y @ [We1|We2]  (bf16 store)
    if (!last) {
#pragma unroll
        for (int half = 0; half < 2; half++) {
            __syncthreads();                 // A ready / NW-write of prev half done
            copy_w64(sm, half, t);           // We1 then We2
            __syncthreads();
            float accp[2][4][4];
            acc_zero64(accp);
            mainloop64<true>(smb, accp, lane, wm, wn);
            __syncthreads();
            stage64(smS, accp, lane, wm, wn);
            __syncthreads();
#pragma unroll
            for (int rr = 0; rr < 8; rr++) {
                int r = wid * 8 + rr;
                int n = n0 + r;
                if (n < NN) {
                    float4 v = *(const float4*)(smS + r * LDC + lane * 4);
                    uint2 h = make_uint2(cvt2(v.y, v.x), cvt2(v.w, v.z));
                    *(uint2*)(g_NWb + (size_t)n * 128 + half * 64 + lane * 2) = h;
                }
            }
        }
    }
}

// ------- k_global: 512 threads, k-loop split 4 ways + smem reduction ----------
__global__ void __launch_bounds__(512) k_global(const float* __restrict__ Wg_w,
                                                const float* __restrict__ Wg_b,
                                                const float* __restrict__ We_w,
                                                const float* __restrict__ We_b,
                                                const float* __restrict__ Wn_w,
                                                const float* __restrict__ Wn_b,
                                                int last)
{
    int g = blockIdx.x;
    int t = threadIdx.x;
    int j = t & 127, q = t >> 7;            // q in 0..3, k-range [32q, 32q+32)
    __shared__ float nm[D], em[D], uu[D], un[D];
    __shared__ float red[4][D], redE[4][D], redN[4][D];

    if (q == 0) {
        float inv = 1.f / fmaxf(g_cntg[g], 1.f);
        float nmv = g_gsum_node[g * D + j] * inv;
        float emv = g_gsum_ebar[g * D + j] * inv;
        nm[j] = nmv; em[j] = emv;
        uu[j] = g_u[g * D + j];
        g_nm[g * D + j] = nmv;
        g_em[g * D + j] = emv;
        g_gsum_node[g * D + j] = 0.f;       // reset for next pass
        g_gsum_ebar[g * D + j] = 0.f;
    }
    __syncthreads();

    float acc = 0.f;
    int k0 = q * 32;
#pragma unroll 4
    for (int k = k0; k < k0 + 32; k++) {
        acc = fmaf(nm[k], Wg_w[k * D + j], acc);
        acc = fmaf(em[k], Wg_w[(D + k) * D + j], acc);
        acc = fmaf(uu[k], Wg_w[(2 * D + k) * D + j], acc);
    }
    red[q][j] = acc;
    __syncthreads();

    if (q == 0) {
        float s = Wg_b[j] + red[0][j] + red[1][j] + red[2][j] + red[3][j];
        float r = fmaxf(s, 0.f);
        g_u[g * D + j] = r;
        un[j] = r;
    }
    if (last) return;                        // uproj values dead after final pass
    __syncthreads();

    float aE = 0.f, aN = 0.f;
#pragma unroll 4
    for (int k = k0; k < k0 + 32; k++) {
        float uv = un[k];
        aE = fmaf(uv, We_w[(3 * D + k) * D + j], aE);
        aN = fmaf(uv, Wn_w[(2 * D + k) * D + j], aN);
    }
    redE[q][j] = aE;
    redN[q][j] = aN;
    __syncthreads();

    if (q == 0) {
        g_uprojE[g * D + j] = We_b[j] + redE[0][j] + redE[1][j] + redE[2][j] + redE[3][j];
        g_uprojN[g * D + j] = Wn_b[j] + redN[0][j] + redN[1][j] + redN[2][j] + redN[3][j];
    }
}

__global__ void k_readout(const float* __restrict__ lin_w, const float* __restrict__ lin_b,
                          float* __restrict__ out)
{
    int g = blockIdx.x, t = threadIdx.x;
    __shared__ float pooled[3 * D];
    pooled[t]         = g_nm[g * D + t];
    pooled[D + t]     = g_em[g * D + t];
    pooled[2 * D + t] = g_u[g * D + t];
    __syncthreads();
    if (t < NCLS) {
        float acc = lin_b[t];
#pragma unroll 4
        for (int k = 0; k < 3 * D; k++) acc = fmaf(pooled[k], lin_w[k * NCLS + t], acc);
        out[g * NCLS + t] = acc;
    }
}

// ---------------- host launcher ----------------------------------------------
extern "C" void kernel_launch(void* const* d_in, const int* in_sizes, int n_in,
                              void* d_out, int out_size)
{
    const float* node_in = (const float*)d_in[0];
    const float* edge_in = (const float*)d_in[1];
    const float* u_in    = (const float*)d_in[2];
    const int*   ei      = (const int*)d_in[3];
    const int*   batch   = (const int*)d_in[4];
    const float* We_w = (const float*)d_in[5];
    const float* We_b = (const float*)d_in[6];
    const float* Wn_w = (const float*)d_in[7];
    const float* Wn_b = (const float*)d_in[8];
    const float* Wg_w = (const float*)d_in[9];
    const float* Wg_b = (const float*)d_in[10];
    const float* lin_w = (const float*)d_in[11];
    const float* lin_b = (const float*)d_in[12];
    float* out = (float*)d_out;

    float* p_node = nullptr;
    cudaGetSymbolAddress((void**)&p_node, g_node);

    cudaFuncSetAttribute(k_proj,            cudaFuncAttributeMaxDynamicSharedMemorySize, SM64);
    cudaFuncSetAttribute(k_edge_tc<false>,  cudaFuncAttributeMaxDynamicSharedMemorySize, SM64);
    cudaFuncSetAttribute(k_edge_tc<true>,   cudaFuncAttributeMaxDynamicSharedMemorySize, SM64);
    cudaFuncSetAttribute(k_node,            cudaFuncAttributeMaxDynamicSharedMemorySize, SM64);

    int nsm = 148;
    cudaDeviceGetAttribute(&nsm, cudaDevAttrMultiProcessorCount, 0);
    int gp = 2 * nsm;   // persistent grid for edge kernel

    k_setup<<<325, 256>>>(u_in, We_w, We_b, Wn_w, Wn_b);   // 0
    k_hist<<<(NE + 255) / 256, 256>>>(ei, batch);          // 1
    k_proj<<<NT64, 256, SM64>>>(node_in);                  // 2 (once)

    const float* nsrc = node_in;
    for (int p = 0; p < 3; p++) {
        int last = (p == 2);
        if (p == 0) k_edge_tc<false><<<gp, 256, SM64>>>(edge_in, ei, batch, last); // 3 <- profiled
        else        k_edge_tc<true><<<gp, 256, SM64>>>(nullptr, ei, batch, last);
        k_node<<<NT64, 256, SM64>>>(nsrc, batch, last);
        k_global<<<NG, 512>>>(Wg_w, Wg_b, We_w, We_b, Wn_w, Wn_b, last);
        nsrc = p_node;
    }
    k_readout<<<NG, D>>>(lin_w, lin_b, out);
}